// round 2
// baseline (speedup 1.0000x reference)
#include <cuda_runtime.h>
#include <math.h>

// Problem constants
#define Nn    20000
#define Ee    320000
#define RNAd  2000
#define PROTd 100
#define EMBd  256
#define HIDd  128
#define NH    4
#define HDd   512
#define INWd  2100

// ---------------- scratch (device globals: allocation-free) ----------------
__device__ float    g_h0  [(size_t)Nn * HDd];
__device__ float    g_xs  [(size_t)Nn * HDd];
__device__ float    g_xd  [(size_t)Nn * HDd];
__device__ float    g_buf [(size_t)Nn * HDd];
__device__ float    g_asrc[Nn * NH];
__device__ float    g_adst[Nn * NH];
__device__ unsigned g_max [Nn * NH];
__device__ float    g_den [Nn * NH];
__device__ float    g_eval[(size_t)Ee * NH];

// ---------------- SGEMM: C = A@B (+bias1 +bias2) (+relu) ----------------
#define BM 128
#define BN 128
#define BK 8

__global__ __launch_bounds__(256) void sgemm_k(
    const float* __restrict__ A, int lda,
    const float* __restrict__ B, int ldb,
    float* __restrict__ C, int ldc,
    const float* __restrict__ bias1, const float* __restrict__ bias2,
    int M, int N, int K, int act)
{
    __shared__ float As[BK][BM];
    __shared__ float Bs[BK][BN];

    const int tid = threadIdx.x;
    const int bm  = blockIdx.y * BM;
    const int bn  = blockIdx.x * BN;
    const int tx  = tid & 15;          // 16 threads along N
    const int ty  = tid >> 4;          // 16 threads along M
    const int arow = tid >> 1;         // 0..127
    const int acol = (tid & 1) << 2;   // 0 or 4
    const int brow = tid >> 5;         // 0..7
    const int bcol = (tid & 31) << 2;  // 0..124

    float acc[8][8];
    #pragma unroll
    for (int i = 0; i < 8; i++)
        #pragma unroll
        for (int j = 0; j < 8; j++) acc[i][j] = 0.f;

    for (int k0 = 0; k0 < K; k0 += BK) {
        // --- load A tile (BM x BK), transposed into As ---
        float4 av = make_float4(0.f, 0.f, 0.f, 0.f);
        {
            int gr = bm + arow;
            int gk = k0 + acol;
            if (gr < M) {
                if (gk + 3 < K) {
                    av = *reinterpret_cast<const float4*>(A + (size_t)gr * lda + gk);
                } else {
                    float t[4] = {0.f, 0.f, 0.f, 0.f};
                    #pragma unroll
                    for (int i = 0; i < 4; i++)
                        if (gk + i < K) t[i] = A[(size_t)gr * lda + gk + i];
                    av = make_float4(t[0], t[1], t[2], t[3]);
                }
            }
        }
        As[acol + 0][arow] = av.x;
        As[acol + 1][arow] = av.y;
        As[acol + 2][arow] = av.z;
        As[acol + 3][arow] = av.w;

        // --- load B tile (BK x BN) ---
        float4 bv = make_float4(0.f, 0.f, 0.f, 0.f);
        {
            int gk = k0 + brow;
            int gc = bn + bcol;
            if (gk < K) {
                if (gc + 3 < N) {
                    bv = *reinterpret_cast<const float4*>(B + (size_t)gk * ldb + gc);
                } else {
                    float t[4] = {0.f, 0.f, 0.f, 0.f};
                    #pragma unroll
                    for (int i = 0; i < 4; i++)
                        if (gc + i < N) t[i] = B[(size_t)gk * ldb + gc + i];
                    bv = make_float4(t[0], t[1], t[2], t[3]);
                }
            }
        }
        *reinterpret_cast<float4*>(&Bs[brow][bcol]) = bv;

        __syncthreads();

        #pragma unroll
        for (int k = 0; k < BK; k++) {
            float ar[8], br[8];
            *reinterpret_cast<float4*>(&ar[0]) = *reinterpret_cast<float4*>(&As[k][ty * 8]);
            *reinterpret_cast<float4*>(&ar[4]) = *reinterpret_cast<float4*>(&As[k][ty * 8 + 4]);
            *reinterpret_cast<float4*>(&br[0]) = *reinterpret_cast<float4*>(&Bs[k][tx * 8]);
            *reinterpret_cast<float4*>(&br[4]) = *reinterpret_cast<float4*>(&Bs[k][tx * 8 + 4]);
            #pragma unroll
            for (int i = 0; i < 8; i++)
                #pragma unroll
                for (int j = 0; j < 8; j++)
                    acc[i][j] += ar[i] * br[j];
        }
        __syncthreads();
    }

    #pragma unroll
    for (int i = 0; i < 8; i++) {
        int row = bm + ty * 8 + i;
        if (row >= M) continue;
        #pragma unroll
        for (int j = 0; j < 8; j++) {
            int col = bn + tx * 8 + j;
            if (col >= N) continue;
            float v = acc[i][j];
            if (bias1) v += bias1[col];
            if (bias2) v += bias2[col];
            if (act)   v = fmaxf(v, 0.f);
            C[(size_t)row * ldc + col] = v;
        }
    }
}

// ---------------- order-preserving float<->uint for atomicMax ----------------
__device__ __forceinline__ unsigned fenc(float f) {
    unsigned u = __float_as_uint(f);
    return (u & 0x80000000u) ? ~u : (u | 0x80000000u);
}
__device__ __forceinline__ float fdec(unsigned u) {
    return (u & 0x80000000u) ? __uint_as_float(u & 0x7fffffffu) : __uint_as_float(~u);
}

// ---------------- GAT helper kernels ----------------
// a_src[n,h] = dot(xs[n,h,:], a_s[h,:]) ; same for dst side. One warp per (node, head).
__global__ void attn_coef_k(const float* __restrict__ xs, const float* __restrict__ xd,
                            const float* __restrict__ a_s, const float* __restrict__ a_d,
                            float* __restrict__ asrc, float* __restrict__ adst)
{
    int node = blockIdx.x;
    int lane = threadIdx.x & 31;
    int h    = threadIdx.x >> 5;   // 4 warps = 4 heads

    const float4* xp = reinterpret_cast<const float4*>(xs + (size_t)node * HDd + h * HIDd);
    const float4* ap = reinterpret_cast<const float4*>(a_s + h * HIDd);
    float4 v = xp[lane];
    float4 a = ap[lane];
    float s = v.x * a.x + v.y * a.y + v.z * a.z + v.w * a.w;

    const float4* yp = reinterpret_cast<const float4*>(xd + (size_t)node * HDd + h * HIDd);
    const float4* bp = reinterpret_cast<const float4*>(a_d + h * HIDd);
    float4 w = yp[lane];
    float4 b = bp[lane];
    float t = w.x * b.x + w.y * b.y + w.z * b.z + w.w * b.w;

    #pragma unroll
    for (int o = 16; o; o >>= 1) {
        s += __shfl_xor_sync(0xffffffffu, s, o);
        t += __shfl_xor_sync(0xffffffffu, t, o);
    }
    if (lane == 0) {
        asrc[node * NH + h] = s;
        adst[node * NH + h] = t;
    }
}

__global__ void init_md_k(unsigned* __restrict__ mx, float* __restrict__ den)
{
    int i = blockIdx.x * blockDim.x + threadIdx.x;
    if (i < Nn * NH) { mx[i] = 0u; den[i] = 0.f; }
}

// pass 1: e = leaky_relu(a_src[src]+a_dst[dst]); store; segment atomicMax over dst
__global__ void edge_max_k(const int* __restrict__ src, const int* __restrict__ dst,
                           const float* __restrict__ asrc, const float* __restrict__ adst,
                           float* __restrict__ eval, unsigned* __restrict__ mx)
{
    int idx = blockIdx.x * blockDim.x + threadIdx.x;
    if (idx >= Ee * NH) return;
    int e = idx >> 2, h = idx & 3;
    int s = src[e], d = dst[e];
    float v = asrc[s * NH + h] + adst[d * NH + h];
    v = v > 0.f ? v : 0.2f * v;
    eval[idx] = v;
    atomicMax(&mx[d * NH + h], fenc(v));
}

// pass 2: exp(e - max[dst]); accumulate denominator
__global__ void edge_exp_k(const int* __restrict__ dst,
                           float* __restrict__ eval, const unsigned* __restrict__ mx,
                           float* __restrict__ den)
{
    int idx = blockIdx.x * blockDim.x + threadIdx.x;
    if (idx >= Ee * NH) return;
    int e = idx >> 2, h = idx & 3;
    int d = dst[e];
    float m  = fdec(mx[d * NH + h]);
    float ex = expf(eval[idx] - m);
    eval[idx] = ex;
    atomicAdd(&den[d * NH + h], ex);
}

// pass 3: out[dst,h,:] += alpha * xs[src,h,:]   (one warp per (edge, head))
__global__ void scatter_k(const int* __restrict__ src, const int* __restrict__ dst,
                          const float* __restrict__ eval, const float* __restrict__ den,
                          const float* __restrict__ xs, float* __restrict__ out)
{
    long long gw = ((long long)blockIdx.x * blockDim.x + threadIdx.x) >> 5;
    int lane = threadIdx.x & 31;
    if (gw >= (long long)Ee * NH) return;
    int e = (int)(gw >> 2), h = (int)(gw & 3);
    int s = src[e], d = dst[e];
    float alpha = eval[gw] / (den[d * NH + h] + 1e-16f);
    float4 v = reinterpret_cast<const float4*>(xs + (size_t)s * HDd + h * HIDd)[lane];
    float* op = out + (size_t)d * HDd + h * HIDd + lane * 4;
    atomicAdd(op + 0, v.x * alpha);
    atomicAdd(op + 1, v.y * alpha);
    atomicAdd(op + 2, v.z * alpha);
    atomicAdd(op + 3, v.w * alpha);
}

__global__ void relu_k(float* __restrict__ p, int n)
{
    int i = blockIdx.x * blockDim.x + threadIdx.x;
    if (i < n) p[i] = fmaxf(p[i], 0.f);
}

// ---------------- host helpers ----------------
static inline void gemm(const float* A, int lda, const float* B, int ldb,
                        float* C, int ldc, const float* b1, const float* b2,
                        int M, int N, int K, int act)
{
    dim3 grid((N + BN - 1) / BN, (M + BM - 1) / BM);
    sgemm_k<<<grid, 256>>>(A, lda, B, ldb, C, ldc, b1, b2, M, N, K, act);
}

static void run_gat(const float* h, const float* ws, const float* wd,
                    const float* a_s, const float* a_d, const float* gb,
                    const float* lw, const float* lb,
                    const int* src, const int* dst,
                    float* xs, float* xd, float* outb,
                    float* asrc, float* adst, unsigned* mx, float* den, float* eval)
{
    gemm(h, HDd, ws, HDd, xs, HDd, nullptr, nullptr, Nn, HDd, HDd, 0);
    gemm(h, HDd, wd, HDd, xd, HDd, nullptr, nullptr, Nn, HDd, HDd, 0);
    attn_coef_k<<<Nn, 128>>>(xs, xd, a_s, a_d, asrc, adst);
    init_md_k<<<(Nn * NH + 255) / 256, 256>>>(mx, den);
    edge_max_k<<<(Ee * NH + 255) / 256, 256>>>(src, dst, asrc, adst, eval, mx);
    edge_exp_k<<<(Ee * NH + 255) / 256, 256>>>(dst, eval, mx, den);
    // linear residual part first (initializes the accumulation buffer):
    // outb = h @ lw + gb + lb
    gemm(h, HDd, lw, HDd, outb, HDd, gb, lb, Nn, HDd, HDd, 0);
    // then scatter the attention messages on top
    scatter_k<<<(int)(((long long)Ee * NH * 32 + 255) / 256), 256>>>(src, dst, eval, den, xs, outb);
    relu_k<<<(Nn * HDd + 255) / 256, 256>>>(outb, Nn * HDd);
}

extern "C" void kernel_launch(void* const* d_in, const int* in_sizes, int n_in,
                              void* d_out, int out_size)
{
    const float* x      = (const float*)d_in[0];
    const int*   ei     = (const int*)  d_in[1];
    const float* W_rna  = (const float*)d_in[2];
    const float* b_rna  = (const float*)d_in[3];
    const float* W_prot = (const float*)d_in[4];
    const float* b_prot = (const float*)d_in[5];
    const float* g1_ws  = (const float*)d_in[6];
    const float* g1_wd  = (const float*)d_in[7];
    const float* g1_as  = (const float*)d_in[8];
    const float* g1_ad  = (const float*)d_in[9];
    const float* g1_b   = (const float*)d_in[10];
    const float* l1_w   = (const float*)d_in[11];
    const float* l1_b   = (const float*)d_in[12];
    const float* g2_ws  = (const float*)d_in[13];
    const float* g2_wd  = (const float*)d_in[14];
    const float* g2_as  = (const float*)d_in[15];
    const float* g2_ad  = (const float*)d_in[16];
    const float* g2_b   = (const float*)d_in[17];
    const float* l2_w   = (const float*)d_in[18];
    const float* l2_b   = (const float*)d_in[19];
    const float* agg_w  = (const float*)d_in[20];
    const float* agg_b  = (const float*)d_in[21];
    const float* dr_w   = (const float*)d_in[22];
    const float* dr_b   = (const float*)d_in[23];
    const float* dp_w   = (const float*)d_in[24];
    const float* dp_b   = (const float*)d_in[25];
    const float* rr_w   = (const float*)d_in[26];
    const float* rr_b   = (const float*)d_in[27];
    const float* rp_w   = (const float*)d_in[28];
    const float* rp_b   = (const float*)d_in[29];

    const int* src = ei;
    const int* dst = ei + Ee;

    float* out = (float*)d_out;
    float* out_rna  = out;                 // [Nn, 2000]
    float* out_prot = out + (size_t)Nn * RNAd;                 // [Nn, 100]
    float* out_emb  = out + (size_t)Nn * (RNAd + PROTd);       // [Nn, 128]

    float *h0, *xs, *xd, *buf, *asrc, *adst, *den, *eval;
    unsigned* mx;
    cudaGetSymbolAddress((void**)&h0,   g_h0);
    cudaGetSymbolAddress((void**)&xs,   g_xs);
    cudaGetSymbolAddress((void**)&xd,   g_xd);
    cudaGetSymbolAddress((void**)&buf,  g_buf);
    cudaGetSymbolAddress((void**)&asrc, g_asrc);
    cudaGetSymbolAddress((void**)&adst, g_adst);
    cudaGetSymbolAddress((void**)&mx,   g_max);
    cudaGetSymbolAddress((void**)&den,  g_den);
    cudaGetSymbolAddress((void**)&eval, g_eval);

    // 1) input embeddings: h0 = [x[:, :2000] @ W_rna + b_rna | x[:, 2000:] @ W_prot + b_prot]
    gemm(x,        INWd, W_rna,  EMBd, h0,        HDd, b_rna,  nullptr, Nn, EMBd, RNAd,  0);
    gemm(x + RNAd, INWd, W_prot, EMBd, h0 + EMBd, HDd, b_prot, nullptr, Nn, EMBd, PROTd, 0);

    // 2) GAT layer 1: buf = relu(gat(h0) + h0@l1_w + l1_b)
    run_gat(h0, g1_ws, g1_wd, g1_as, g1_ad, g1_b, l1_w, l1_b,
            src, dst, xs, xd, buf, asrc, adst, mx, den, eval);

    // 3) GAT layer 2: h0 = relu(gat(buf) + buf@l2_w + l2_b)   (reuse h0 as h2)
    run_gat(buf, g2_ws, g2_wd, g2_as, g2_ad, g2_b, l2_w, l2_b,
            src, dst, xs, xd, h0, asrc, adst, mx, den, eval);

    // 4) embedding = relu(h2 @ agg_w + agg_b)  -> output region
    gemm(h0, HDd, agg_w, HIDd, out_emb, HIDd, agg_b, nullptr, Nn, HIDd, HDd, 1);

    // 5) decoders (reuse xs/xd as [Nn, 256] scratch)
    gemm(out_emb, HIDd, dr_w, EMBd, xs, EMBd, dr_b, nullptr, Nn, EMBd, HIDd, 0);
    gemm(out_emb, HIDd, dp_w, EMBd, xd, EMBd, dp_b, nullptr, Nn, EMBd, HIDd, 0);

    // 6) reconstructions -> output regions
    gemm(xs, EMBd, rr_w, RNAd,  out_rna,  RNAd,  rr_b, nullptr, Nn, RNAd,  EMBd, 0);
    gemm(xd, EMBd, rp_w, PROTd, out_prot, PROTd, rp_b, nullptr, Nn, PROTd, EMBd, 0);
}

// round 4
// speedup vs baseline: 1.3101x; 1.3101x over previous
#include <cuda_runtime.h>
#include <math.h>
#include <stdint.h>

// Problem constants
#define Nn    20000
#define Ee    320000
#define RNAd  2000
#define PROTd 100
#define EMBd  256
#define HIDd  128
#define NH    4
#define HDd   512
#define INWd  2100

// ---------------- scratch (device globals: allocation-free) ----------------
__device__ float    g_h0  [(size_t)Nn * HDd];
__device__ float    g_xs  [(size_t)Nn * HDd];
__device__ float    g_xd  [(size_t)Nn * HDd];
__device__ float    g_buf [(size_t)Nn * HDd];
__device__ float    g_asrc[Nn * NH];
__device__ float    g_adst[Nn * NH];
__device__ unsigned g_max [Nn * NH];
__device__ float    g_den [Nn * NH];
__device__ float    g_eval[(size_t)Ee * NH];

// ============================================================================
// TF32 mma.sync GEMM:  C[M,N] = A[M,K] @ B[K,N] (+bias1 +bias2) (+relu)
// Block tile 128x128x16, 8 warps, warp tile 64x32, mma.m16n8k8.tf32.
// Shared memory holds tiles in *fragment order* so that:
//   - global->shared stores are conflict-free STS.64
//   - shared->register fragment loads are conflict-free LDS.64
// ============================================================================

__device__ __forceinline__ float f2tf32(float x) {
    uint32_t u;
    asm("cvt.rna.tf32.f32 %0, %1;" : "=r"(u) : "f"(x));
    return __uint_as_float(u);
}

__device__ __forceinline__ void mma_tf32(float* d, const uint32_t* a, const uint32_t* b) {
    asm volatile(
        "mma.sync.aligned.m16n8k8.row.col.f32.tf32.tf32.f32 "
        "{%0,%1,%2,%3}, {%4,%5,%6,%7}, {%8,%9}, {%0,%1,%2,%3};"
        : "+f"(d[0]), "+f"(d[1]), "+f"(d[2]), "+f"(d[3])
        : "r"(a[0]), "r"(a[1]), "r"(a[2]), "r"(a[3]), "r"(b[0]), "r"(b[1]));
}

// A frag smem: [buf][ks(2)][rbit(2)][mt(8)][lane(32)][kcbit(2)]  (2048 floats/buf)
// B frag smem: [buf][ks(2)][nt(16)][66]  where slot = lane*2 + bit, 2 pad (2112/buf)
#define ABUF 2048
#define BBUF 2112

__global__ __launch_bounds__(256, 1) void mma_gemm_k(
    const float* __restrict__ A, int lda,
    const float* __restrict__ B, int ldb,
    float* __restrict__ C, int ldc,
    const float* __restrict__ bias1, const float* __restrict__ bias2,
    int M, int N, int K, int act)
{
    __shared__ float As[2 * ABUF];
    __shared__ float Bs[2 * BBUF];

    const int tid  = threadIdx.x;
    const int lane = tid & 31;
    const int warp = tid >> 5;
    const int wm   = warp >> 2;    // 0..1  (64-row slab)
    const int wn   = warp & 3;     // 0..3  (32-col slab)
    const int bm   = blockIdx.y * 128;
    const int bn   = blockIdx.x * 128;

    // A loader mapping: it in {0,1}: row = tid/4 + 64*it, j = tid&3, kc = j + 4s
    const int arow0 = tid >> 2;
    const int aj    = tid & 3;
    // B loader mapping: it in {0,1}: c = tid/128 + 2*it, n = tid&127, kc = c + 4s
    const int bc0 = tid >> 7;
    const int bnn = tid & 127;

    float a_reg[2][4], b_reg[2][4];
    float acc[4][4][4];
    #pragma unroll
    for (int i = 0; i < 4; i++)
        #pragma unroll
        for (int j = 0; j < 4; j++)
            #pragma unroll
            for (int r = 0; r < 4; r++) acc[i][j][r] = 0.f;

    const int KT = (K + 15) >> 4;

    // ---- prologue: load tile 0 ----
    {
        const int k0 = 0;
        #pragma unroll
        for (int it = 0; it < 2; it++) {
            int row = arow0 + it * 64;
            bool rok = (bm + row) < M;
            const float* ap = A + (size_t)(bm + row) * lda + k0;
            #pragma unroll
            for (int s = 0; s < 4; s++) {
                int kc = aj + 4 * s;
                a_reg[it][s] = (rok && kc < K) ? __ldg(ap + kc) : 0.f;
            }
            int c = bc0 + it * 2;
            bool nok = (bn + bnn) < N;
            #pragma unroll
            for (int s = 0; s < 4; s++) {
                int kc = c + 4 * s;
                b_reg[it][s] = (nok && kc < K) ? __ldg(B + (size_t)kc * ldb + bn + bnn) : 0.f;
            }
        }
    }

    for (int t = 0; t < KT; t++) {
        const int buf = t & 1;

        // ---- store prefetched regs into smem buffer `buf` (fragment order) ----
        #pragma unroll
        for (int it = 0; it < 2; it++) {
            int row = arow0 + it * 64;
            int mt  = row >> 4;
            int rb  = (row >> 3) & 1;
            int lf  = ((row & 7) << 2) | aj;
            float2* d0 = (float2*)&As[buf * ABUF + (((0 * 2 + rb) * 8 + mt) * 32 + lf) * 2];
            float2* d1 = (float2*)&As[buf * ABUF + (((1 * 2 + rb) * 8 + mt) * 32 + lf) * 2];
            *d0 = make_float2(f2tf32(a_reg[it][0]), f2tf32(a_reg[it][1]));
            *d1 = make_float2(f2tf32(a_reg[it][2]), f2tf32(a_reg[it][3]));

            int c  = bc0 + it * 2;
            int nt = bnn >> 3;
            int lb = ((bnn & 7) << 2) | c;
            float2* e0 = (float2*)&Bs[buf * BBUF + 0 * 1056 + nt * 66 + lb * 2];
            float2* e1 = (float2*)&Bs[buf * BBUF + 1 * 1056 + nt * 66 + lb * 2];
            *e0 = make_float2(f2tf32(b_reg[it][0]), f2tf32(b_reg[it][1]));
            *e1 = make_float2(f2tf32(b_reg[it][2]), f2tf32(b_reg[it][3]));
        }
        __syncthreads();

        // ---- prefetch next tile gmem -> regs ----
        if (t + 1 < KT) {
            const int k0 = (t + 1) << 4;
            #pragma unroll
            for (int it = 0; it < 2; it++) {
                int row = arow0 + it * 64;
                bool rok = (bm + row) < M;
                const float* ap = A + (size_t)(bm + row) * lda + k0;
                #pragma unroll
                for (int s = 0; s < 4; s++) {
                    int kc = aj + 4 * s;
                    a_reg[it][s] = (rok && (k0 + kc) < K) ? __ldg(ap + kc) : 0.f;
                }
                int c = bc0 + it * 2;
                bool nok = (bn + bnn) < N;
                #pragma unroll
                for (int s = 0; s < 4; s++) {
                    int kc = c + 4 * s;
                    b_reg[it][s] = (nok && (k0 + kc) < K) ? __ldg(B + (size_t)(k0 + kc) * ldb + bn + bnn) : 0.f;
                }
            }
        }

        // ---- compute from smem buffer `buf` ----
        #pragma unroll
        for (int ks = 0; ks < 2; ks++) {
            uint32_t af[4][4];
            #pragma unroll
            for (int i = 0; i < 4; i++) {
                int mt = wm * 4 + i;
                float2 p0 = *(float2*)&As[buf * ABUF + ((ks * 2 + 0) * 8 + mt) * 64 + lane * 2];
                float2 p1 = *(float2*)&As[buf * ABUF + ((ks * 2 + 1) * 8 + mt) * 64 + lane * 2];
                af[i][0] = __float_as_uint(p0.x);
                af[i][2] = __float_as_uint(p0.y);
                af[i][1] = __float_as_uint(p1.x);
                af[i][3] = __float_as_uint(p1.y);
            }
            uint32_t bf[4][2];
            #pragma unroll
            for (int j = 0; j < 4; j++) {
                int nt = wn * 4 + j;
                float2 q = *(float2*)&Bs[buf * BBUF + ks * 1056 + nt * 66 + lane * 2];
                bf[j][0] = __float_as_uint(q.x);
                bf[j][1] = __float_as_uint(q.y);
            }
            #pragma unroll
            for (int i = 0; i < 4; i++)
                #pragma unroll
                for (int j = 0; j < 4; j++)
                    mma_tf32(acc[i][j], af[i], bf[j]);
        }
        __syncthreads();
    }

    // ---- epilogue ----
    #pragma unroll
    for (int i = 0; i < 4; i++) {
        int row0 = bm + wm * 64 + i * 16 + (lane >> 2);
        #pragma unroll
        for (int j = 0; j < 4; j++) {
            int col0 = bn + wn * 32 + j * 8 + ((lane & 3) << 1);
            float bv0 = 0.f, bv1 = 0.f;
            if (col0 < N) {
                if (bias1) bv0 += bias1[col0];
                if (bias2) bv0 += bias2[col0];
            }
            if (col0 + 1 < N) {
                if (bias1) bv1 += bias1[col0 + 1];
                if (bias2) bv1 += bias2[col0 + 1];
            }
            #pragma unroll
            for (int h = 0; h < 2; h++) {
                int row = row0 + 8 * h;
                if (row >= M) continue;
                float v0 = acc[i][j][2 * h + 0] + bv0;
                float v1 = acc[i][j][2 * h + 1] + bv1;
                if (act) { v0 = fmaxf(v0, 0.f); v1 = fmaxf(v1, 0.f); }
                float* cp = C + (size_t)row * ldc + col0;
                if (col0 + 1 < N)      *(float2*)cp = make_float2(v0, v1);
                else if (col0 < N)     *cp = v0;
            }
        }
    }
}

// ---------------- order-preserving float<->uint for atomicMax ----------------
__device__ __forceinline__ unsigned fenc(float f) {
    unsigned u = __float_as_uint(f);
    return (u & 0x80000000u) ? ~u : (u | 0x80000000u);
}
__device__ __forceinline__ float fdec(unsigned u) {
    return (u & 0x80000000u) ? __uint_as_float(u & 0x7fffffffu) : __uint_as_float(~u);
}

// ---------------- GAT helper kernels ----------------
__global__ void attn_coef_k(const float* __restrict__ xs, const float* __restrict__ xd,
                            const float* __restrict__ a_s, const float* __restrict__ a_d,
                            float* __restrict__ asrc, float* __restrict__ adst)
{
    int node = blockIdx.x;
    int lane = threadIdx.x & 31;
    int h    = threadIdx.x >> 5;

    const float4* xp = reinterpret_cast<const float4*>(xs + (size_t)node * HDd + h * HIDd);
    const float4* ap = reinterpret_cast<const float4*>(a_s + h * HIDd);
    float4 v = xp[lane];
    float4 a = ap[lane];
    float s = v.x * a.x + v.y * a.y + v.z * a.z + v.w * a.w;

    const float4* yp = reinterpret_cast<const float4*>(xd + (size_t)node * HDd + h * HIDd);
    const float4* bp = reinterpret_cast<const float4*>(a_d + h * HIDd);
    float4 w = yp[lane];
    float4 b = bp[lane];
    float t = w.x * b.x + w.y * b.y + w.z * b.z + w.w * b.w;

    #pragma unroll
    for (int o = 16; o; o >>= 1) {
        s += __shfl_xor_sync(0xffffffffu, s, o);
        t += __shfl_xor_sync(0xffffffffu, t, o);
    }
    if (lane == 0) {
        asrc[node * NH + h] = s;
        adst[node * NH + h] = t;
    }
}

__global__ void init_md_k(unsigned* __restrict__ mx, float* __restrict__ den)
{
    int i = blockIdx.x * blockDim.x + threadIdx.x;
    if (i < Nn * NH) { mx[i] = 0u; den[i] = 0.f; }
}

__global__ void edge_max_k(const int* __restrict__ src, const int* __restrict__ dst,
                           const float* __restrict__ asrc, const float* __restrict__ adst,
                           float* __restrict__ eval, unsigned* __restrict__ mx)
{
    int idx = blockIdx.x * blockDim.x + threadIdx.x;
    if (idx >= Ee * NH) return;
    int e = idx >> 2, h = idx & 3;
    int s = src[e], d = dst[e];
    float v = asrc[s * NH + h] + adst[d * NH + h];
    v = v > 0.f ? v : 0.2f * v;
    eval[idx] = v;
    atomicMax(&mx[d * NH + h], fenc(v));
}

__global__ void edge_exp_k(const int* __restrict__ dst,
                           float* __restrict__ eval, const unsigned* __restrict__ mx,
                           float* __restrict__ den)
{
    int idx = blockIdx.x * blockDim.x + threadIdx.x;
    if (idx >= Ee * NH) return;
    int e = idx >> 2, h = idx & 3;
    int d = dst[e];
    float m  = fdec(mx[d * NH + h]);
    float ex = expf(eval[idx] - m);
    eval[idx] = ex;
    atomicAdd(&den[d * NH + h], ex);
}

__global__ void scatter_k(const int* __restrict__ src, const int* __restrict__ dst,
                          const float* __restrict__ eval, const float* __restrict__ den,
                          const float* __restrict__ xs, float* __restrict__ out)
{
    long long gw = ((long long)blockIdx.x * blockDim.x + threadIdx.x) >> 5;
    int lane = threadIdx.x & 31;
    if (gw >= (long long)Ee * NH) return;
    int e = (int)(gw >> 2), h = (int)(gw & 3);
    int s = src[e], d = dst[e];
    float alpha = eval[gw] / (den[d * NH + h] + 1e-16f);
    float4 v = reinterpret_cast<const float4*>(xs + (size_t)s * HDd + h * HIDd)[lane];
    float* op = out + (size_t)d * HDd + h * HIDd + lane * 4;
    atomicAdd(op + 0, v.x * alpha);
    atomicAdd(op + 1, v.y * alpha);
    atomicAdd(op + 2, v.z * alpha);
    atomicAdd(op + 3, v.w * alpha);
}

__global__ void relu_k(float* __restrict__ p, int n)
{
    int i = blockIdx.x * blockDim.x + threadIdx.x;
    if (i < n) p[i] = fmaxf(p[i], 0.f);
}

// ---------------- host helpers ----------------
static inline void gemm(const float* A, int lda, const float* B, int ldb,
                        float* C, int ldc, const float* b1, const float* b2,
                        int M, int N, int K, int act)
{
    dim3 grid((N + 127) / 128, (M + 127) / 128);
    mma_gemm_k<<<grid, 256>>>(A, lda, B, ldb, C, ldc, b1, b2, M, N, K, act);
}

static void run_gat(const float* h, const float* ws, const float* wd,
                    const float* a_s, const float* a_d, const float* gb,
                    const float* lw, const float* lb,
                    const int* src, const int* dst,
                    float* xs, float* xd, float* outb,
                    float* asrc, float* adst, unsigned* mx, float* den, float* eval)
{
    gemm(h, HDd, ws, HDd, xs, HDd, nullptr, nullptr, Nn, HDd, HDd, 0);
    gemm(h, HDd, wd, HDd, xd, HDd, nullptr, nullptr, Nn, HDd, HDd, 0);
    attn_coef_k<<<Nn, 128>>>(xs, xd, a_s, a_d, asrc, adst);
    init_md_k<<<(Nn * NH + 255) / 256, 256>>>(mx, den);
    edge_max_k<<<(Ee * NH + 255) / 256, 256>>>(src, dst, asrc, adst, eval, mx);
    edge_exp_k<<<(Ee * NH + 255) / 256, 256>>>(dst, eval, mx, den);
    gemm(h, HDd, lw, HDd, outb, HDd, gb, lb, Nn, HDd, HDd, 0);
    scatter_k<<<(int)(((long long)Ee * NH * 32 + 255) / 256), 256>>>(src, dst, eval, den, xs, outb);
    relu_k<<<(Nn * HDd + 255) / 256, 256>>>(outb, Nn * HDd);
}

extern "C" void kernel_launch(void* const* d_in, const int* in_sizes, int n_in,
                              void* d_out, int out_size)
{
    const float* x      = (const float*)d_in[0];
    const int*   ei     = (const int*)  d_in[1];
    const float* W_rna  = (const float*)d_in[2];
    const float* b_rna  = (const float*)d_in[3];
    const float* W_prot = (const float*)d_in[4];
    const float* b_prot = (const float*)d_in[5];
    const float* g1_ws  = (const float*)d_in[6];
    const float* g1_wd  = (const float*)d_in[7];
    const float* g1_as  = (const float*)d_in[8];
    const float* g1_ad  = (const float*)d_in[9];
    const float* g1_b   = (const float*)d_in[10];
    const float* l1_w   = (const float*)d_in[11];
    const float* l1_b   = (const float*)d_in[12];
    const float* g2_ws  = (const float*)d_in[13];
    const float* g2_wd  = (const float*)d_in[14];
    const float* g2_as  = (const float*)d_in[15];
    const float* g2_ad  = (const float*)d_in[16];
    const float* g2_b   = (const float*)d_in[17];
    const float* l2_w   = (const float*)d_in[18];
    const float* l2_b   = (const float*)d_in[19];
    const float* agg_w  = (const float*)d_in[20];
    const float* agg_b  = (const float*)d_in[21];
    const float* dr_w   = (const float*)d_in[22];
    const float* dr_b   = (const float*)d_in[23];
    const float* dp_w   = (const float*)d_in[24];
    const float* dp_b   = (const float*)d_in[25];
    const float* rr_w   = (const float*)d_in[26];
    const float* rr_b   = (const float*)d_in[27];
    const float* rp_w   = (const float*)d_in[28];
    const float* rp_b   = (const float*)d_in[29];

    const int* src = ei;
    const int* dst = ei + Ee;

    float* out = (float*)d_out;
    float* out_rna  = out;                                     // [Nn, 2000]
    float* out_prot = out + (size_t)Nn * RNAd;                 // [Nn, 100]
    float* out_emb  = out + (size_t)Nn * (RNAd + PROTd);       // [Nn, 128]

    float *h0, *xs, *xd, *buf, *asrc, *adst, *den, *eval;
    unsigned* mx;
    cudaGetSymbolAddress((void**)&h0,   g_h0);
    cudaGetSymbolAddress((void**)&xs,   g_xs);
    cudaGetSymbolAddress((void**)&xd,   g_xd);
    cudaGetSymbolAddress((void**)&buf,  g_buf);
    cudaGetSymbolAddress((void**)&asrc, g_asrc);
    cudaGetSymbolAddress((void**)&adst, g_adst);
    cudaGetSymbolAddress((void**)&mx,   g_max);
    cudaGetSymbolAddress((void**)&den,  g_den);
    cudaGetSymbolAddress((void**)&eval, g_eval);

    // 1) input embeddings
    gemm(x,        INWd, W_rna,  EMBd, h0,        HDd, b_rna,  nullptr, Nn, EMBd, RNAd,  0);
    gemm(x + RNAd, INWd, W_prot, EMBd, h0 + EMBd, HDd, b_prot, nullptr, Nn, EMBd, PROTd, 0);

    // 2) GAT layer 1
    run_gat(h0, g1_ws, g1_wd, g1_as, g1_ad, g1_b, l1_w, l1_b,
            src, dst, xs, xd, buf, asrc, adst, mx, den, eval);

    // 3) GAT layer 2
    run_gat(buf, g2_ws, g2_wd, g2_as, g2_ad, g2_b, l2_w, l2_b,
            src, dst, xs, xd, h0, asrc, adst, mx, den, eval);

    // 4) embedding
    gemm(h0, HDd, agg_w, HIDd, out_emb, HIDd, agg_b, nullptr, Nn, HIDd, HDd, 1);

    // 5) decoders
    gemm(out_emb, HIDd, dr_w, EMBd, xs, EMBd, dr_b, nullptr, Nn, EMBd, HIDd, 0);
    gemm(out_emb, HIDd, dp_w, EMBd, xd, EMBd, dp_b, nullptr, Nn, EMBd, HIDd, 0);

    // 6) reconstructions
    gemm(xs, EMBd, rr_w, RNAd,  out_rna,  RNAd,  rr_b, nullptr, Nn, RNAd,  EMBd, 0);
    gemm(xd, EMBd, rp_w, PROTd, out_prot, PROTd, rp_b, nullptr, Nn, PROTd, EMBd, 0);
}

// round 6
// speedup vs baseline: 2.9647x; 2.2629x over previous
#include <cuda_runtime.h>
#include <math.h>
#include <stdint.h>

// Problem constants
#define Nn    20000
#define Ee    320000
#define RNAd  2000
#define PROTd 100
#define EMBd  256
#define HIDd  128
#define NH    4
#define HDd   512
#define INWd  2100

// ---------------- scratch (device globals: allocation-free) ----------------
__device__ float    g_h0  [(size_t)Nn * HDd];
__device__ float    g_xs  [(size_t)Nn * HDd];
__device__ float    g_xd  [(size_t)Nn * HDd];
__device__ float    g_buf [(size_t)Nn * HDd];
__device__ float    g_asrc[Nn * NH];
__device__ float    g_adst[Nn * NH];
__device__ float    g_inv [Nn * NH];
__device__ float    g_eval[(size_t)Ee * NH];
__device__ float    g_xr  [(size_t)Nn * INWd];   // tf32-rounded input x
__device__ float    g_wr  [3000000];             // tf32-rounded weights
__device__ float    g_embr[(size_t)Nn * HIDd];   // rounded embedding for decoders
__device__ int      g_deg [Nn];
__device__ int      g_cur [Nn];
__device__ int      g_roff[Nn + 1];
__device__ int      g_eord[Ee];

__device__ __forceinline__ float f2tf32(float x) {
    uint32_t u;
    asm("cvt.rna.tf32.f32 %0, %1;" : "=r"(u) : "f"(x));
    return __uint_as_float(u);
}

__device__ __forceinline__ void mma_tf32(float* d, const uint32_t* a, const uint32_t* b) {
    asm volatile(
        "mma.sync.aligned.m16n8k8.row.col.f32.tf32.tf32.f32 "
        "{%0,%1,%2,%3}, {%4,%5,%6,%7}, {%8,%9}, {%0,%1,%2,%3};"
        : "+f"(d[0]), "+f"(d[1]), "+f"(d[2]), "+f"(d[3])
        : "r"(a[0]), "r"(a[1]), "r"(a[2]), "r"(a[3]), "r"(b[0]), "r"(b[1]));
}

// ---------------- elementwise tf32 rounding pass ----------------
__global__ void round_k(const float4* __restrict__ in, float4* __restrict__ out, int n4)
{
    int i = blockIdx.x * blockDim.x + threadIdx.x;
    if (i < n4) {
        float4 v = in[i];
        out[i] = make_float4(f2tf32(v.x), f2tf32(v.y), f2tf32(v.z), f2tf32(v.w));
    }
}

// ============================================================================
// TF32 mma.sync GEMM (inputs pre-rounded to tf32).
// Block tile 128x128x16, 8 warps, warp tile 64x32, double-buffered smem in
// fragment order (conflict-free STS.64 / LDS.64).
// ============================================================================
#define ABUF 2048
#define BBUF 2112

__global__ __launch_bounds__(256, 2) void mma_gemm_k(
    const float* __restrict__ A, int lda,
    const float* __restrict__ B, int ldb,
    float* __restrict__ C, int ldc,
    const float* __restrict__ bias1, const float* __restrict__ bias2,
    int M, int N, int K, int act, int round_c, float* __restrict__ Cr)
{
    __shared__ float As[2 * ABUF];
    __shared__ float Bs[2 * BBUF];

    const int tid  = threadIdx.x;
    const int lane = tid & 31;
    const int warp = tid >> 5;
    const int wm   = warp >> 2;
    const int wn   = warp & 3;
    const int bm   = blockIdx.y * 128;
    const int bn   = blockIdx.x * 128;

    const int arow0 = tid >> 2;
    const int aj    = tid & 3;
    const int bc0 = tid >> 7;
    const int bnn = tid & 127;

    float a_reg[2][4], b_reg[2][4];
    float acc[4][4][4];
    #pragma unroll
    for (int i = 0; i < 4; i++)
        #pragma unroll
        for (int j = 0; j < 4; j++)
            #pragma unroll
            for (int r = 0; r < 4; r++) acc[i][j][r] = 0.f;

    const int KT = (K + 15) >> 4;

    {
        #pragma unroll
        for (int it = 0; it < 2; it++) {
            int row = arow0 + it * 64;
            bool rok = (bm + row) < M;
            const float* ap = A + (size_t)(bm + row) * lda;
            #pragma unroll
            for (int s = 0; s < 4; s++) {
                int kc = aj + 4 * s;
                a_reg[it][s] = (rok && kc < K) ? __ldg(ap + kc) : 0.f;
            }
            int c = bc0 + it * 2;
            bool nok = (bn + bnn) < N;
            #pragma unroll
            for (int s = 0; s < 4; s++) {
                int kc = c + 4 * s;
                b_reg[it][s] = (nok && kc < K) ? __ldg(B + (size_t)kc * ldb + bn + bnn) : 0.f;
            }
        }
    }

    for (int t = 0; t < KT; t++) {
        const int buf = t & 1;

        #pragma unroll
        for (int it = 0; it < 2; it++) {
            int row = arow0 + it * 64;
            int mt  = row >> 4;
            int rb  = (row >> 3) & 1;
            int lf  = ((row & 7) << 2) | aj;
            float2* d0 = (float2*)&As[buf * ABUF + (((0 * 2 + rb) * 8 + mt) * 32 + lf) * 2];
            float2* d1 = (float2*)&As[buf * ABUF + (((1 * 2 + rb) * 8 + mt) * 32 + lf) * 2];
            *d0 = make_float2(a_reg[it][0], a_reg[it][1]);
            *d1 = make_float2(a_reg[it][2], a_reg[it][3]);

            int c  = bc0 + it * 2;
            int nt = bnn >> 3;
            int lb = ((bnn & 7) << 2) | c;
            float2* e0 = (float2*)&Bs[buf * BBUF + 0 * 1056 + nt * 66 + lb * 2];
            float2* e1 = (float2*)&Bs[buf * BBUF + 1 * 1056 + nt * 66 + lb * 2];
            *e0 = make_float2(b_reg[it][0], b_reg[it][1]);
            *e1 = make_float2(b_reg[it][2], b_reg[it][3]);
        }
        __syncthreads();

        if (t + 1 < KT) {
            const int k0 = (t + 1) << 4;
            #pragma unroll
            for (int it = 0; it < 2; it++) {
                int row = arow0 + it * 64;
                bool rok = (bm + row) < M;
                const float* ap = A + (size_t)(bm + row) * lda + k0;
                #pragma unroll
                for (int s = 0; s < 4; s++) {
                    int kc = aj + 4 * s;
                    a_reg[it][s] = (rok && (k0 + kc) < K) ? __ldg(ap + kc) : 0.f;
                }
                int c = bc0 + it * 2;
                bool nok = (bn + bnn) < N;
                #pragma unroll
                for (int s = 0; s < 4; s++) {
                    int kc = c + 4 * s;
                    b_reg[it][s] = (nok && (k0 + kc) < K) ? __ldg(B + (size_t)(k0 + kc) * ldb + bn + bnn) : 0.f;
                }
            }
        }

        #pragma unroll
        for (int ks = 0; ks < 2; ks++) {
            uint32_t af[4][4];
            #pragma unroll
            for (int i = 0; i < 4; i++) {
                int mt = wm * 4 + i;
                float2 p0 = *(float2*)&As[buf * ABUF + ((ks * 2 + 0) * 8 + mt) * 64 + lane * 2];
                float2 p1 = *(float2*)&As[buf * ABUF + ((ks * 2 + 1) * 8 + mt) * 64 + lane * 2];
                af[i][0] = __float_as_uint(p0.x);
                af[i][2] = __float_as_uint(p0.y);
                af[i][1] = __float_as_uint(p1.x);
                af[i][3] = __float_as_uint(p1.y);
            }
            uint32_t bf[4][2];
            #pragma unroll
            for (int j = 0; j < 4; j++) {
                int nt = wn * 4 + j;
                float2 q = *(float2*)&Bs[buf * BBUF + ks * 1056 + nt * 66 + lane * 2];
                bf[j][0] = __float_as_uint(q.x);
                bf[j][1] = __float_as_uint(q.y);
            }
            #pragma unroll
            for (int i = 0; i < 4; i++)
                #pragma unroll
                for (int j = 0; j < 4; j++)
                    mma_tf32(acc[i][j], af[i], bf[j]);
        }
        __syncthreads();
    }

    // ---- epilogue ----
    #pragma unroll
    for (int i = 0; i < 4; i++) {
        int row0 = bm + wm * 64 + i * 16 + (lane >> 2);
        #pragma unroll
        for (int j = 0; j < 4; j++) {
            int col0 = bn + wn * 32 + j * 8 + ((lane & 3) << 1);
            float bv0 = 0.f, bv1 = 0.f;
            if (col0 < N) {
                if (bias1) bv0 += bias1[col0];
                if (bias2) bv0 += bias2[col0];
            }
            if (col0 + 1 < N) {
                if (bias1) bv1 += bias1[col0 + 1];
                if (bias2) bv1 += bias2[col0 + 1];
            }
            #pragma unroll
            for (int h = 0; h < 2; h++) {
                int row = row0 + 8 * h;
                if (row >= M) continue;
                float v0 = acc[i][j][2 * h + 0] + bv0;
                float v1 = acc[i][j][2 * h + 1] + bv1;
                if (act) { v0 = fmaxf(v0, 0.f); v1 = fmaxf(v1, 0.f); }
                float w0 = round_c ? f2tf32(v0) : v0;
                float w1 = round_c ? f2tf32(v1) : v1;
                float* cp = C + (size_t)row * ldc + col0;
                if (col0 + 1 < N) {
                    *(float2*)cp = make_float2(w0, w1);
                    if (Cr) *(float2*)(Cr + (size_t)row * ldc + col0) =
                                make_float2(f2tf32(v0), f2tf32(v1));
                } else if (col0 < N) {
                    *cp = w0;
                    if (Cr) Cr[(size_t)row * ldc + col0] = f2tf32(v0);
                }
            }
        }
    }
}

// ---------------- GAT: attention coefficients ----------------
__global__ void attn_coef_k(const float* __restrict__ xs, const float* __restrict__ xd,
                            const float* __restrict__ a_s, const float* __restrict__ a_d,
                            float* __restrict__ asrc, float* __restrict__ adst)
{
    int node = blockIdx.x;
    int lane = threadIdx.x & 31;
    int h    = threadIdx.x >> 5;

    const float4* xp = reinterpret_cast<const float4*>(xs + (size_t)node * HDd + h * HIDd);
    const float4* ap = reinterpret_cast<const float4*>(a_s + h * HIDd);
    float4 v = xp[lane];
    float4 a = ap[lane];
    float s = v.x * a.x + v.y * a.y + v.z * a.z + v.w * a.w;

    const float4* yp = reinterpret_cast<const float4*>(xd + (size_t)node * HDd + h * HIDd);
    const float4* bp = reinterpret_cast<const float4*>(a_d + h * HIDd);
    float4 w = yp[lane];
    float4 b = bp[lane];
    float t = w.x * b.x + w.y * b.y + w.z * b.z + w.w * b.w;

    #pragma unroll
    for (int o = 16; o; o >>= 1) {
        s += __shfl_xor_sync(0xffffffffu, s, o);
        t += __shfl_xor_sync(0xffffffffu, t, o);
    }
    if (lane == 0) {
        asrc[node * NH + h] = s;
        adst[node * NH + h] = t;
    }
}

// ---------------- CSR build (once per launch) ----------------
__global__ void zero_deg_k(int* __restrict__ deg)
{
    int i = blockIdx.x * blockDim.x + threadIdx.x;
    if (i < Nn) deg[i] = 0;
}

__global__ void hist_k(const int* __restrict__ dst, int* __restrict__ deg)
{
    int e = blockIdx.x * blockDim.x + threadIdx.x;
    if (e < Ee) atomicAdd(&deg[dst[e]], 1);
}

#define SCAN_T 1024
#define SCAN_C 20   // 1024*20 = 20480 >= Nn
__global__ __launch_bounds__(SCAN_T) void scan_k(const int* __restrict__ deg,
                                                 int* __restrict__ roff,
                                                 int* __restrict__ cur)
{
    __shared__ int ss[SCAN_T];
    int t = threadIdx.x;
    int base = t * SCAN_C;
    int loc[SCAN_C];
    int sum = 0;
    #pragma unroll
    for (int i = 0; i < SCAN_C; i++) {
        int idx = base + i;
        int v = (idx < Nn) ? deg[idx] : 0;
        loc[i] = sum;
        sum += v;
    }
    ss[t] = sum;
    __syncthreads();
    int own = sum;
    for (int off = 1; off < SCAN_T; off <<= 1) {
        int v = (t >= off) ? ss[t - off] : 0;
        __syncthreads();
        ss[t] += v;
        __syncthreads();
    }
    int excl = ss[t] - own;
    #pragma unroll
    for (int i = 0; i < SCAN_C; i++) {
        int idx = base + i;
        if (idx < Nn) { roff[idx] = excl + loc[i]; cur[idx] = excl + loc[i]; }
    }
    if (t == SCAN_T - 1) roff[Nn] = ss[SCAN_T - 1];
}

__global__ void bucket_k(const int* __restrict__ dst, int* __restrict__ cur,
                         int* __restrict__ eord)
{
    int e = blockIdx.x * blockDim.x + threadIdx.x;
    if (e < Ee) {
        int pos = atomicAdd(&cur[dst[e]], 1);
        eord[pos] = e;
    }
}

// ---------------- segment softmax: per (node, head) warp, no atomics -------
__global__ __launch_bounds__(128) void softmax_k(
    const int* __restrict__ src, const int* __restrict__ eord,
    const int* __restrict__ roff,
    const float* __restrict__ asrc, const float* __restrict__ adst,
    float* __restrict__ eval, float* __restrict__ inv)
{
    int n    = blockIdx.x;
    int h    = threadIdx.x >> 5;
    int lane = threadIdx.x & 31;
    int r0 = roff[n], r1 = roff[n + 1];
    float adn = adst[n * NH + h];

    float m = -3.4e38f;
    for (int j = r0 + lane; j < r1; j += 32) {
        int eid = eord[j];
        float v = asrc[src[eid] * NH + h] + adn;
        v = v > 0.f ? v : 0.2f * v;
        m = fmaxf(m, v);
    }
    #pragma unroll
    for (int o = 16; o; o >>= 1) m = fmaxf(m, __shfl_xor_sync(0xffffffffu, m, o));

    float s = 0.f;
    for (int j = r0 + lane; j < r1; j += 32) {
        int eid = eord[j];
        float v = asrc[src[eid] * NH + h] + adn;
        v = v > 0.f ? v : 0.2f * v;
        float ex = expf(v - m);
        eval[(size_t)eid * NH + h] = ex;
        s += ex;
    }
    #pragma unroll
    for (int o = 16; o; o >>= 1) s += __shfl_xor_sync(0xffffffffu, s, o);

    if (lane == 0)
        inv[n * NH + h] = (r1 > r0) ? 1.f / (s + 1e-16f) : 0.f;
}

// ---------------- gather-aggregate + residual + ReLU + tf32 round ----------
// block = node, 4 warps = 4 heads; lane covers 4 feats (float4).
__global__ __launch_bounds__(128) void aggregate_k(
    const int* __restrict__ src, const int* __restrict__ eord,
    const int* __restrict__ roff,
    const float* __restrict__ eval, const float* __restrict__ inv,
    const float* __restrict__ xs, float* __restrict__ out)
{
    int n    = blockIdx.x;
    int h    = threadIdx.x >> 5;
    int lane = threadIdx.x & 31;
    int r0 = roff[n], r1 = roff[n + 1];

    float4 acc = make_float4(0.f, 0.f, 0.f, 0.f);
    for (int j = r0; j < r1; j++) {
        int eid = eord[j];
        int s   = src[eid];
        float a = eval[(size_t)eid * NH + h];
        float4 v = *reinterpret_cast<const float4*>(xs + (size_t)s * HDd + h * HIDd + lane * 4);
        acc.x += a * v.x; acc.y += a * v.y; acc.z += a * v.z; acc.w += a * v.w;
    }
    float iv = inv[n * NH + h];
    float* op = out + (size_t)n * HDd + h * HIDd + lane * 4;
    float4 o = *reinterpret_cast<float4*>(op);
    o.x = f2tf32(fmaxf(o.x + acc.x * iv, 0.f));
    o.y = f2tf32(fmaxf(o.y + acc.y * iv, 0.f));
    o.z = f2tf32(fmaxf(o.z + acc.z * iv, 0.f));
    o.w = f2tf32(fmaxf(o.w + acc.w * iv, 0.f));
    *reinterpret_cast<float4*>(op) = o;
}

// ---------------- host helpers ----------------
static inline void gemm(const float* A, int lda, const float* B, int ldb,
                        float* C, int ldc, const float* b1, const float* b2,
                        int M, int N, int K, int act, int round_c = 0, float* Cr = nullptr)
{
    dim3 grid((N + 127) / 128, (M + 127) / 128);
    mma_gemm_k<<<grid, 256>>>(A, lda, B, ldb, C, ldc, b1, b2, M, N, K, act, round_c, Cr);
}

static void run_gat(const float* h, const float* ws, const float* wd,
                    const float* a_s, const float* a_d, const float* gb,
                    const float* lw, const float* lb,
                    const int* src, const int* eord, const int* roff,
                    float* xs, float* xd, float* outb,
                    float* asrc, float* adst, float* inv, float* eval)
{
    gemm(h, HDd, ws, HDd, xs, HDd, nullptr, nullptr, Nn, HDd, HDd, 0);
    gemm(h, HDd, wd, HDd, xd, HDd, nullptr, nullptr, Nn, HDd, HDd, 0);
    attn_coef_k<<<Nn, 128>>>(xs, xd, a_s, a_d, asrc, adst);
    softmax_k<<<Nn, 128>>>(src, eord, roff, asrc, adst, eval, inv);
    gemm(h, HDd, lw, HDd, outb, HDd, gb, lb, Nn, HDd, HDd, 0);
    aggregate_k<<<Nn, 128>>>(src, eord, roff, eval, inv, xs, outb);
}

extern "C" void kernel_launch(void* const* d_in, const int* in_sizes, int n_in,
                              void* d_out, int out_size)
{
    const float* x      = (const float*)d_in[0];
    const int*   ei     = (const int*)  d_in[1];
    const float* W_rna  = (const float*)d_in[2];
    const float* b_rna  = (const float*)d_in[3];
    const float* W_prot = (const float*)d_in[4];
    const float* b_prot = (const float*)d_in[5];
    const float* g1_ws  = (const float*)d_in[6];
    const float* g1_wd  = (const float*)d_in[7];
    const float* g1_as  = (const float*)d_in[8];
    const float* g1_ad  = (const float*)d_in[9];
    const float* g1_b   = (const float*)d_in[10];
    const float* l1_w   = (const float*)d_in[11];
    const float* l1_b   = (const float*)d_in[12];
    const float* g2_ws  = (const float*)d_in[13];
    const float* g2_wd  = (const float*)d_in[14];
    const float* g2_as  = (const float*)d_in[15];
    const float* g2_ad  = (const float*)d_in[16];
    const float* g2_b   = (const float*)d_in[17];
    const float* l2_w   = (const float*)d_in[18];
    const float* l2_b   = (const float*)d_in[19];
    const float* agg_w  = (const float*)d_in[20];
    const float* agg_b  = (const float*)d_in[21];
    const float* dr_w   = (const float*)d_in[22];
    const float* dr_b   = (const float*)d_in[23];
    const float* dp_w   = (const float*)d_in[24];
    const float* dp_b   = (const float*)d_in[25];
    const float* rr_w   = (const float*)d_in[26];
    const float* rr_b   = (const float*)d_in[27];
    const float* rp_w   = (const float*)d_in[28];
    const float* rp_b   = (const float*)d_in[29];

    const int* src = ei;
    const int* dst = ei + Ee;

    float* out = (float*)d_out;
    float* out_rna  = out;                                     // [Nn, 2000]
    float* out_prot = out + (size_t)Nn * RNAd;                 // [Nn, 100]
    float* out_emb  = out + (size_t)Nn * (RNAd + PROTd);       // [Nn, 128]

    float *h0, *xs, *xd, *buf, *asrc, *adst, *inv, *eval, *xr, *wr, *embr;
    int *deg, *cur, *roff, *eord;
    cudaGetSymbolAddress((void**)&h0,   g_h0);
    cudaGetSymbolAddress((void**)&xs,   g_xs);
    cudaGetSymbolAddress((void**)&xd,   g_xd);
    cudaGetSymbolAddress((void**)&buf,  g_buf);
    cudaGetSymbolAddress((void**)&asrc, g_asrc);
    cudaGetSymbolAddress((void**)&adst, g_adst);
    cudaGetSymbolAddress((void**)&inv,  g_inv);
    cudaGetSymbolAddress((void**)&eval, g_eval);
    cudaGetSymbolAddress((void**)&xr,   g_xr);
    cudaGetSymbolAddress((void**)&wr,   g_wr);
    cudaGetSymbolAddress((void**)&embr, g_embr);
    cudaGetSymbolAddress((void**)&deg,  g_deg);
    cudaGetSymbolAddress((void**)&cur,  g_cur);
    cudaGetSymbolAddress((void**)&roff, g_roff);
    cudaGetSymbolAddress((void**)&eord, g_eord);

    // ---- pre-round inputs to tf32 ----
    auto roundp = [](const float* in, float* dst, size_t n) {
        int n4 = (int)(n >> 2);
        round_k<<<(n4 + 255) / 256, 256>>>((const float4*)in, (float4*)dst, n4);
    };
    roundp(x, xr, (size_t)Nn * INWd);

    size_t wo = 0;
    auto roundw = [&](const float* w, size_t n) -> float* {
        float* d = wr + wo;
        roundp(w, d, n);
        wo += n;
        return d;
    };
    float* W_rna_r  = roundw(W_rna,  (size_t)RNAd * EMBd);
    float* W_prot_r = roundw(W_prot, (size_t)PROTd * EMBd);
    float* g1_ws_r  = roundw(g1_ws,  (size_t)2 * EMBd * HDd);
    float* g1_wd_r  = roundw(g1_wd,  (size_t)2 * EMBd * HDd);
    float* l1_w_r   = roundw(l1_w,   (size_t)2 * EMBd * HDd);
    float* g2_ws_r  = roundw(g2_ws,  (size_t)HDd * HDd);
    float* g2_wd_r  = roundw(g2_wd,  (size_t)HDd * HDd);
    float* l2_w_r   = roundw(l2_w,   (size_t)HDd * HDd);
    float* agg_w_r  = roundw(agg_w,  (size_t)HDd * HIDd);
    float* dr_w_r   = roundw(dr_w,   (size_t)HIDd * EMBd);
    float* dp_w_r   = roundw(dp_w,   (size_t)HIDd * EMBd);
    float* rr_w_r   = roundw(rr_w,   (size_t)EMBd * RNAd);
    float* rp_w_r   = roundw(rp_w,   (size_t)EMBd * PROTd);

    // ---- CSR build (dst-sorted edge order) ----
    zero_deg_k<<<(Nn + 255) / 256, 256>>>(deg);
    hist_k<<<(Ee + 255) / 256, 256>>>(dst, deg);
    scan_k<<<1, SCAN_T>>>(deg, roff, cur);
    bucket_k<<<(Ee + 255) / 256, 256>>>(dst, cur, eord);

    // 1) input embeddings: h0 = [xr[:, :2000]@W_rna + b_rna | xr[:, 2000:]@W_prot + b_prot]
    gemm(xr,        INWd, W_rna_r,  EMBd, h0,        HDd, b_rna,  nullptr, Nn, EMBd, RNAd,  0, 1);
    gemm(xr + RNAd, INWd, W_prot_r, EMBd, h0 + EMBd, HDd, b_prot, nullptr, Nn, EMBd, PROTd, 0, 1);

    // 2) GAT layer 1: buf = round(relu(gat(h0) + h0@l1_w + l1_b))
    run_gat(h0, g1_ws_r, g1_wd_r, g1_as, g1_ad, g1_b, l1_w_r, l1_b,
            src, eord, roff, xs, xd, buf, asrc, adst, inv, eval);

    // 3) GAT layer 2: h0 = round(relu(gat(buf) + buf@l2_w + l2_b))
    run_gat(buf, g2_ws_r, g2_wd_r, g2_as, g2_ad, g2_b, l2_w_r, l2_b,
            src, eord, roff, xs, xd, h0, asrc, adst, inv, eval);

    // 4) embedding = relu(h2 @ agg_w + agg_b) -> output (exact) + rounded copy
    gemm(h0, HDd, agg_w_r, HIDd, out_emb, HIDd, agg_b, nullptr, Nn, HIDd, HDd, 1, 0, embr);

    // 5) decoders (rounded outputs; feed recon GEMMs)
    gemm(embr, HIDd, dr_w_r, EMBd, xs, EMBd, dr_b, nullptr, Nn, EMBd, HIDd, 0, 1);
    gemm(embr, HIDd, dp_w_r, EMBd, xd, EMBd, dp_b, nullptr, Nn, EMBd, HIDd, 0, 1);

    // 6) reconstructions
    gemm(xs, EMBd, rr_w_r, RNAd,  out_rna,  RNAd,  rr_b, nullptr, Nn, RNAd,  EMBd, 0);
    gemm(xd, EMBd, rp_w_r, PROTd, out_prot, PROTd, rp_b, nullptr, Nn, PROTd, EMBd, 0);
}

// round 8
// speedup vs baseline: 3.4376x; 1.1595x over previous
#include <cuda_runtime.h>
#include <math.h>
#include <stdint.h>

// Problem constants
#define Nn    20000
#define Ee    320000
#define RNAd  2000
#define PROTd 100
#define EMBd  256
#define HIDd  128
#define NH    4
#define HDd   512
#define INWd  2100

// ---------------- scratch (device globals: allocation-free) ----------------
__device__ float    g_h0  [(size_t)Nn * HDd];    // layer activations
__device__ float    g_xs  [(size_t)Nn * HDd];    // decoder scratch (reuse)
__device__ float    g_buf [(size_t)Nn * HDd];    // layer activations
__device__ float    g_fz  [(size_t)Nn * 1024];   // fused GEMM out: [xs | residual]
__device__ float    g_asrc[Nn * NH];
__device__ float    g_adst[Nn * NH];
__device__ float    g_inv [Nn * NH];
__device__ float    g_eval[(size_t)Ee * NH];
__device__ float    g_wr  [3000000];             // rounded/packed weights
__device__ float    g_embr[(size_t)Nn * HIDd];   // rounded embedding for decoders
__device__ int      g_deg [Nn];
__device__ int      g_cur [Nn];
__device__ int      g_roff[Nn + 1];
__device__ int      g_eord[Ee];

__device__ __forceinline__ float f2tf32(float x) {
    uint32_t u;
    asm("cvt.rna.tf32.f32 %0, %1;" : "=r"(u) : "f"(x));
    return __uint_as_float(u);
}

__device__ __forceinline__ void mma_tf32(float* d, const uint32_t* a, const uint32_t* b) {
    asm volatile(
        "mma.sync.aligned.m16n8k8.row.col.f32.tf32.tf32.f32 "
        "{%0,%1,%2,%3}, {%4,%5,%6,%7}, {%8,%9}, {%0,%1,%2,%3};"
        : "+f"(d[0]), "+f"(d[1]), "+f"(d[2]), "+f"(d[3])
        : "r"(a[0]), "r"(a[1]), "r"(a[2]), "r"(a[3]), "r"(b[0]), "r"(b[1]));
}

// ---------------- elementwise tf32 rounding pass (weights) ----------------
__global__ void round_k(const float4* __restrict__ in, float4* __restrict__ out, int n4)
{
    int i = blockIdx.x * blockDim.x + threadIdx.x;
    if (i < n4) {
        float4 v = in[i];
        out[i] = make_float4(f2tf32(v.x), f2tf32(v.y), f2tf32(v.z), f2tf32(v.w));
    }
}

// ---------------- pack [ws | lw] -> Bfused[512][1024], rounded ----------------
__global__ void pack_k(const float* __restrict__ ws, const float* __restrict__ lw,
                       float* __restrict__ bf)
{
    int idx = blockIdx.x * blockDim.x + threadIdx.x;   // 512*1024
    if (idx >= 512 * 1024) return;
    int k = idx >> 10, n = idx & 1023;
    float v = (n < 512) ? ws[k * 512 + n] : lw[k * 512 + (n - 512)];
    bf[idx] = f2tf32(v);
}

// ---------------- combined bias: [0(512) | gb+lb] ----------------
__global__ void biasf_k(const float* __restrict__ gb, const float* __restrict__ lb,
                        float* __restrict__ bf)
{
    int i = threadIdx.x;   // 1024 threads
    bf[i] = (i < 512) ? 0.f : (gb[i - 512] + lb[i - 512]);
}

// ---------------- Wattn[8][512]: c<4 -> ws@a_s head c ; c>=4 -> wd@a_d ----
__global__ void wattn_k(const float* __restrict__ ws, const float* __restrict__ wd,
                        const float* __restrict__ a_s, const float* __restrict__ a_d,
                        float* __restrict__ wattn)
{
    int c = blockIdx.x;            // 0..7
    int t = threadIdx.x;           // 0..127
    const float* w = (c < 4) ? ws : wd;
    const float* a = (c < 4) ? (a_s + (c) * HIDd) : (a_d + (c - 4) * HIDd);
    int hh = (c < 4) ? c : (c - 4);
    #pragma unroll
    for (int kq = 0; kq < 4; kq++) {
        int k = t + kq * 128;
        float s = 0.f;
        const float* wr = w + (size_t)k * HDd + hh * HIDd;
        for (int d = 0; d < HIDd; d++) s += wr[d] * a[d];
        wattn[c * HDd + k] = s;
    }
}

// ---------------- attn coefs from h directly: 8 warps = 8 outputs ----------
__global__ __launch_bounds__(256) void attn8_k(
    const float* __restrict__ h, const float* __restrict__ wattn,
    float* __restrict__ asrc, float* __restrict__ adst)
{
    int n    = blockIdx.x;
    int c    = threadIdx.x >> 5;
    int lane = threadIdx.x & 31;
    const float4* hp = reinterpret_cast<const float4*>(h + (size_t)n * HDd);
    const float4* wp = reinterpret_cast<const float4*>(wattn + c * HDd);
    float s = 0.f;
    #pragma unroll
    for (int q = 0; q < 4; q++) {
        float4 a = hp[lane + q * 32];
        float4 b = wp[lane + q * 32];
        s += a.x * b.x + a.y * b.y + a.z * b.z + a.w * b.w;
    }
    #pragma unroll
    for (int o = 16; o; o >>= 1) s += __shfl_xor_sync(0xffffffffu, s, o);
    if (lane == 0) {
        if (c < 4) asrc[n * NH + c]       = s;
        else       adst[n * NH + (c - 4)] = s;
    }
}

// ============================================================================
// TF32 mma.sync GEMM. Block tile 128x128x16, 8 warps, warp tile 64x32.
// round_a: apply tf32 rounding to A at smem-store (for raw-f32 A inputs).
// ============================================================================
#define ABUF 2048
#define BBUF 2112

__global__ __launch_bounds__(256, 2) void mma_gemm_k(
    const float* __restrict__ A, int lda,
    const float* __restrict__ B, int ldb,
    float* __restrict__ C, int ldc,
    const float* __restrict__ bias1,
    int M, int N, int K, int act, int round_a, int round_c, float* __restrict__ Cr)
{
    __shared__ float As[2 * ABUF];
    __shared__ float Bs[2 * BBUF];

    const int tid  = threadIdx.x;
    const int lane = tid & 31;
    const int warp = tid >> 5;
    const int wm   = warp >> 2;
    const int wn   = warp & 3;
    const int bm   = blockIdx.y * 128;
    const int bn   = blockIdx.x * 128;

    const int arow0 = tid >> 2;
    const int aj    = tid & 3;
    const int bc0 = tid >> 7;
    const int bnn = tid & 127;

    float a_reg[2][4], b_reg[2][4];
    float acc[4][4][4];
    #pragma unroll
    for (int i = 0; i < 4; i++)
        #pragma unroll
        for (int j = 0; j < 4; j++)
            #pragma unroll
            for (int r = 0; r < 4; r++) acc[i][j][r] = 0.f;

    const int KT = (K + 15) >> 4;

    {
        #pragma unroll
        for (int it = 0; it < 2; it++) {
            int row = arow0 + it * 64;
            bool rok = (bm + row) < M;
            const float* ap = A + (size_t)(bm + row) * lda;
            #pragma unroll
            for (int s = 0; s < 4; s++) {
                int kc = aj + 4 * s;
                a_reg[it][s] = (rok && kc < K) ? __ldg(ap + kc) : 0.f;
            }
            int c = bc0 + it * 2;
            bool nok = (bn + bnn) < N;
            #pragma unroll
            for (int s = 0; s < 4; s++) {
                int kc = c + 4 * s;
                b_reg[it][s] = (nok && kc < K) ? __ldg(B + (size_t)kc * ldb + bn + bnn) : 0.f;
            }
        }
    }

    for (int t = 0; t < KT; t++) {
        const int buf = t & 1;

        #pragma unroll
        for (int it = 0; it < 2; it++) {
            int row = arow0 + it * 64;
            int mt  = row >> 4;
            int rb  = (row >> 3) & 1;
            int lf  = ((row & 7) << 2) | aj;
            float2* d0 = (float2*)&As[buf * ABUF + (((0 * 2 + rb) * 8 + mt) * 32 + lf) * 2];
            float2* d1 = (float2*)&As[buf * ABUF + (((1 * 2 + rb) * 8 + mt) * 32 + lf) * 2];
            if (round_a) {
                *d0 = make_float2(f2tf32(a_reg[it][0]), f2tf32(a_reg[it][1]));
                *d1 = make_float2(f2tf32(a_reg[it][2]), f2tf32(a_reg[it][3]));
            } else {
                *d0 = make_float2(a_reg[it][0], a_reg[it][1]);
                *d1 = make_float2(a_reg[it][2], a_reg[it][3]);
            }

            int c  = bc0 + it * 2;
            int nt = bnn >> 3;
            int lb = ((bnn & 7) << 2) | c;
            float2* e0 = (float2*)&Bs[buf * BBUF + 0 * 1056 + nt * 66 + lb * 2];
            float2* e1 = (float2*)&Bs[buf * BBUF + 1 * 1056 + nt * 66 + lb * 2];
            *e0 = make_float2(b_reg[it][0], b_reg[it][1]);
            *e1 = make_float2(b_reg[it][2], b_reg[it][3]);
        }
        __syncthreads();

        if (t + 1 < KT) {
            const int k0 = (t + 1) << 4;
            #pragma unroll
            for (int it = 0; it < 2; it++) {
                int row = arow0 + it * 64;
                bool rok = (bm + row) < M;
                const float* ap = A + (size_t)(bm + row) * lda + k0;
                #pragma unroll
                for (int s = 0; s < 4; s++) {
                    int kc = aj + 4 * s;
                    a_reg[it][s] = (rok && (k0 + kc) < K) ? __ldg(ap + kc) : 0.f;
                }
                int c = bc0 + it * 2;
                bool nok = (bn + bnn) < N;
                #pragma unroll
                for (int s = 0; s < 4; s++) {
                    int kc = c + 4 * s;
                    b_reg[it][s] = (nok && (k0 + kc) < K) ? __ldg(B + (size_t)(k0 + kc) * ldb + bn + bnn) : 0.f;
                }
            }
        }

        #pragma unroll
        for (int ks = 0; ks < 2; ks++) {
            uint32_t af[4][4];
            #pragma unroll
            for (int i = 0; i < 4; i++) {
                int mt = wm * 4 + i;
                float2 p0 = *(float2*)&As[buf * ABUF + ((ks * 2 + 0) * 8 + mt) * 64 + lane * 2];
                float2 p1 = *(float2*)&As[buf * ABUF + ((ks * 2 + 1) * 8 + mt) * 64 + lane * 2];
                af[i][0] = __float_as_uint(p0.x);
                af[i][2] = __float_as_uint(p0.y);
                af[i][1] = __float_as_uint(p1.x);
                af[i][3] = __float_as_uint(p1.y);
            }
            uint32_t bf[4][2];
            #pragma unroll
            for (int j = 0; j < 4; j++) {
                int nt = wn * 4 + j;
                float2 q = *(float2*)&Bs[buf * BBUF + ks * 1056 + nt * 66 + lane * 2];
                bf[j][0] = __float_as_uint(q.x);
                bf[j][1] = __float_as_uint(q.y);
            }
            #pragma unroll
            for (int i = 0; i < 4; i++)
                #pragma unroll
                for (int j = 0; j < 4; j++)
                    mma_tf32(acc[i][j], af[i], bf[j]);
        }
        __syncthreads();
    }

    // ---- epilogue ----
    #pragma unroll
    for (int i = 0; i < 4; i++) {
        int row0 = bm + wm * 64 + i * 16 + (lane >> 2);
        #pragma unroll
        for (int j = 0; j < 4; j++) {
            int col0 = bn + wn * 32 + j * 8 + ((lane & 3) << 1);
            float bv0 = 0.f, bv1 = 0.f;
            if (bias1) {
                if (col0 < N)     bv0 = bias1[col0];
                if (col0 + 1 < N) bv1 = bias1[col0 + 1];
            }
            #pragma unroll
            for (int h = 0; h < 2; h++) {
                int row = row0 + 8 * h;
                if (row >= M) continue;
                float v0 = acc[i][j][2 * h + 0] + bv0;
                float v1 = acc[i][j][2 * h + 1] + bv1;
                if (act) { v0 = fmaxf(v0, 0.f); v1 = fmaxf(v1, 0.f); }
                float w0 = round_c ? f2tf32(v0) : v0;
                float w1 = round_c ? f2tf32(v1) : v1;
                float* cp = C + (size_t)row * ldc + col0;
                if (col0 + 1 < N) {
                    *(float2*)cp = make_float2(w0, w1);
                    if (Cr) *(float2*)(Cr + (size_t)row * ldc + col0) =
                                make_float2(f2tf32(v0), f2tf32(v1));
                } else if (col0 < N) {
                    *cp = w0;
                    if (Cr) Cr[(size_t)row * ldc + col0] = f2tf32(v0);
                }
            }
        }
    }
}

// ---------------- CSR build (once per launch) ----------------
__global__ void zero_deg_k(int* __restrict__ deg)
{
    int i = blockIdx.x * blockDim.x + threadIdx.x;
    if (i < Nn) deg[i] = 0;
}

__global__ void hist_k(const int* __restrict__ dst, int* __restrict__ deg)
{
    int e = blockIdx.x * blockDim.x + threadIdx.x;
    if (e < Ee) atomicAdd(&deg[dst[e]], 1);
}

#define SCAN_T 1024
#define SCAN_C 20
__global__ __launch_bounds__(SCAN_T) void scan_k(const int* __restrict__ deg,
                                                 int* __restrict__ roff,
                                                 int* __restrict__ cur)
{
    __shared__ int ss[SCAN_T];
    int t = threadIdx.x;
    int base = t * SCAN_C;
    int loc[SCAN_C];
    int sum = 0;
    #pragma unroll
    for (int i = 0; i < SCAN_C; i++) {
        int idx = base + i;
        int v = (idx < Nn) ? deg[idx] : 0;
        loc[i] = sum;
        sum += v;
    }
    ss[t] = sum;
    __syncthreads();
    int own = sum;
    for (int off = 1; off < SCAN_T; off <<= 1) {
        int v = (t >= off) ? ss[t - off] : 0;
        __syncthreads();
        ss[t] += v;
        __syncthreads();
    }
    int excl = ss[t] - own;
    #pragma unroll
    for (int i = 0; i < SCAN_C; i++) {
        int idx = base + i;
        if (idx < Nn) { roff[idx] = excl + loc[i]; cur[idx] = excl + loc[i]; }
    }
    if (t == SCAN_T - 1) roff[Nn] = ss[SCAN_T - 1];
}

__global__ void bucket_k(const int* __restrict__ dst, int* __restrict__ cur,
                         int* __restrict__ eord)
{
    int e = blockIdx.x * blockDim.x + threadIdx.x;
    if (e < Ee) {
        int pos = atomicAdd(&cur[dst[e]], 1);
        eord[pos] = e;
    }
}

// ---------------- segment softmax: per (node, head) warp, no atomics -------
__global__ __launch_bounds__(128) void softmax_k(
    const int* __restrict__ src, const int* __restrict__ eord,
    const int* __restrict__ roff,
    const float* __restrict__ asrc, const float* __restrict__ adst,
    float* __restrict__ eval, float* __restrict__ inv)
{
    int n    = blockIdx.x;
    int h    = threadIdx.x >> 5;
    int lane = threadIdx.x & 31;
    int r0 = roff[n], r1 = roff[n + 1];
    float adn = adst[n * NH + h];

    float m = -3.4e38f;
    for (int j = r0 + lane; j < r1; j += 32) {
        int eid = eord[j];
        float v = asrc[src[eid] * NH + h] + adn;
        v = v > 0.f ? v : 0.2f * v;
        m = fmaxf(m, v);
    }
    #pragma unroll
    for (int o = 16; o; o >>= 1) m = fmaxf(m, __shfl_xor_sync(0xffffffffu, m, o));

    float s = 0.f;
    for (int j = r0 + lane; j < r1; j += 32) {
        int eid = eord[j];
        float v = asrc[src[eid] * NH + h] + adn;
        v = v > 0.f ? v : 0.2f * v;
        float ex = expf(v - m);
        eval[(size_t)eid * NH + h] = ex;
        s += ex;
    }
    #pragma unroll
    for (int o = 16; o; o >>= 1) s += __shfl_xor_sync(0xffffffffu, s, o);

    if (lane == 0)
        inv[n * NH + h] = (r1 > r0) ? 1.f / (s + 1e-16f) : 0.f;
}

// ---------------- gather-aggregate + residual + ReLU + tf32 round ----------
// fz layout: row stride 1024; cols 0-511 = xs (messages), 512-1023 = residual.
__global__ __launch_bounds__(128) void aggregate_k(
    const int* __restrict__ src, const int* __restrict__ eord,
    const int* __restrict__ roff,
    const float* __restrict__ eval, const float* __restrict__ inv,
    const float* __restrict__ fz, float* __restrict__ out)
{
    int n    = blockIdx.x;
    int h    = threadIdx.x >> 5;
    int lane = threadIdx.x & 31;
    int r0 = roff[n], r1 = roff[n + 1];

    float4 acc = make_float4(0.f, 0.f, 0.f, 0.f);
    for (int j = r0; j < r1; j++) {
        int eid = eord[j];
        int s   = src[eid];
        float a = eval[(size_t)eid * NH + h];
        float4 v = *reinterpret_cast<const float4*>(fz + (size_t)s * 1024 + h * HIDd + lane * 4);
        acc.x += a * v.x; acc.y += a * v.y; acc.z += a * v.z; acc.w += a * v.w;
    }
    float iv = inv[n * NH + h];
    float4 r = *reinterpret_cast<const float4*>(fz + (size_t)n * 1024 + 512 + h * HIDd + lane * 4);
    float4 o;
    o.x = f2tf32(fmaxf(r.x + acc.x * iv, 0.f));
    o.y = f2tf32(fmaxf(r.y + acc.y * iv, 0.f));
    o.z = f2tf32(fmaxf(r.z + acc.z * iv, 0.f));
    o.w = f2tf32(fmaxf(r.w + acc.w * iv, 0.f));
    *reinterpret_cast<float4*>(out + (size_t)n * HDd + h * HIDd + lane * 4) = o;
}

// ---------------- host helpers ----------------
static inline void gemm(const float* A, int lda, const float* B, int ldb,
                        float* C, int ldc, const float* b1,
                        int M, int N, int K, int act,
                        int round_a = 0, int round_c = 0, float* Cr = nullptr)
{
    dim3 grid((N + 127) / 128, (M + 127) / 128);
    mma_gemm_k<<<grid, 256>>>(A, lda, B, ldb, C, ldc, b1, M, N, K, act, round_a, round_c, Cr);
}

extern "C" void kernel_launch(void* const* d_in, const int* in_sizes, int n_in,
                              void* d_out, int out_size)
{
    const float* x      = (const float*)d_in[0];
    const int*   ei     = (const int*)  d_in[1];
    const float* W_rna  = (const float*)d_in[2];
    const float* b_rna  = (const float*)d_in[3];
    const float* W_prot = (const float*)d_in[4];
    const float* b_prot = (const float*)d_in[5];
    const float* g1_ws  = (const float*)d_in[6];
    const float* g1_wd  = (const float*)d_in[7];
    const float* g1_as  = (const float*)d_in[8];
    const float* g1_ad  = (const float*)d_in[9];
    const float* g1_b   = (const float*)d_in[10];
    const float* l1_w   = (const float*)d_in[11];
    const float* l1_b   = (const float*)d_in[12];
    const float* g2_ws  = (const float*)d_in[13];
    const float* g2_wd  = (const float*)d_in[14];
    const float* g2_as  = (const float*)d_in[15];
    const float* g2_ad  = (const float*)d_in[16];
    const float* g2_b   = (const float*)d_in[17];
    const float* l2_w   = (const float*)d_in[18];
    const float* l2_b   = (const float*)d_in[19];
    const float* agg_w  = (const float*)d_in[20];
    const float* agg_b  = (const float*)d_in[21];
    const float* dr_w   = (const float*)d_in[22];
    const float* dr_b   = (const float*)d_in[23];
    const float* dp_w   = (const float*)d_in[24];
    const float* dp_b   = (const float*)d_in[25];
    const float* rr_w   = (const float*)d_in[26];
    const float* rr_b   = (const float*)d_in[27];
    const float* rp_w   = (const float*)d_in[28];
    const float* rp_b   = (const float*)d_in[29];

    const int* src = ei;
    const int* dst = ei + Ee;

    float* out = (float*)d_out;
    float* out_rna  = out;                                     // [Nn, 2000]
    float* out_prot = out + (size_t)Nn * RNAd;                 // [Nn, 100]
    float* out_emb  = out + (size_t)Nn * (RNAd + PROTd);       // [Nn, 128]

    float *h0, *xs, *buf, *fz, *asrc, *adst, *inv, *eval, *wr, *embr;
    int *deg, *cur, *roff, *eord;
    cudaGetSymbolAddress((void**)&h0,   g_h0);
    cudaGetSymbolAddress((void**)&xs,   g_xs);
    cudaGetSymbolAddress((void**)&buf,  g_buf);
    cudaGetSymbolAddress((void**)&fz,   g_fz);
    cudaGetSymbolAddress((void**)&asrc, g_asrc);
    cudaGetSymbolAddress((void**)&adst, g_adst);
    cudaGetSymbolAddress((void**)&inv,  g_inv);
    cudaGetSymbolAddress((void**)&eval, g_eval);
    cudaGetSymbolAddress((void**)&wr,   g_wr);
    cudaGetSymbolAddress((void**)&embr, g_embr);
    cudaGetSymbolAddress((void**)&deg,  g_deg);
    cudaGetSymbolAddress((void**)&cur,  g_cur);
    cudaGetSymbolAddress((void**)&roff, g_roff);
    cudaGetSymbolAddress((void**)&eord, g_eord);

    // ---- rounded / packed weight arena ----
    size_t wo = 0;
    auto arena = [&](size_t n) -> float* { float* p = wr + wo; wo += n; return p; };
    auto roundw = [&](const float* w, size_t n) -> float* {
        float* d = arena(n);
        int n4 = (int)(n >> 2);
        round_k<<<(n4 + 255) / 256, 256>>>((const float4*)w, (float4*)d, n4);
        return d;
    };
    float* W_rna_r  = roundw(W_rna,  (size_t)RNAd * EMBd);
    float* W_prot_r = roundw(W_prot, (size_t)PROTd * EMBd);
    float* agg_w_r  = roundw(agg_w,  (size_t)HDd * HIDd);
    float* dr_w_r   = roundw(dr_w,   (size_t)HIDd * EMBd);
    float* dp_w_r   = roundw(dp_w,   (size_t)HIDd * EMBd);
    float* rr_w_r   = roundw(rr_w,   (size_t)EMBd * RNAd);
    float* rp_w_r   = roundw(rp_w,   (size_t)EMBd * PROTd);

    float* Bf1    = arena((size_t)512 * 1024);
    float* Bf2    = arena((size_t)512 * 1024);
    float* biasf1 = arena(1024);
    float* biasf2 = arena(1024);
    float* watt1  = arena(8 * 512);
    float* watt2  = arena(8 * 512);

    pack_k<<<(512 * 1024 + 255) / 256, 256>>>(g1_ws, l1_w, Bf1);
    pack_k<<<(512 * 1024 + 255) / 256, 256>>>(g2_ws, l2_w, Bf2);
    biasf_k<<<1, 1024>>>(g1_b, l1_b, biasf1);
    biasf_k<<<1, 1024>>>(g2_b, l2_b, biasf2);
    wattn_k<<<8, 128>>>(g1_ws, g1_wd, g1_as, g1_ad, watt1);
    wattn_k<<<8, 128>>>(g2_ws, g2_wd, g2_as, g2_ad, watt2);

    // ---- CSR build (dst-sorted edge order) ----
    zero_deg_k<<<(Nn + 255) / 256, 256>>>(deg);
    hist_k<<<(Ee + 255) / 256, 256>>>(dst, deg);
    scan_k<<<1, SCAN_T>>>(deg, roff, cur);
    bucket_k<<<(Ee + 255) / 256, 256>>>(dst, cur, eord);

    // 1) input embeddings (A=x raw f32, rounded in-kernel)
    gemm(x,        INWd, W_rna_r,  EMBd, h0,        HDd, b_rna,  Nn, EMBd, RNAd,  0, 1, 1);
    gemm(x + RNAd, INWd, W_prot_r, EMBd, h0 + EMBd, HDd, b_prot, Nn, EMBd, PROTd, 0, 1, 1);

    // 2) GAT layer 1
    gemm(h0, HDd, Bf1, 1024, fz, 1024, biasf1, Nn, 1024, HDd, 0);
    attn8_k<<<Nn, 256>>>(h0, watt1, asrc, adst);
    softmax_k<<<Nn, 128>>>(src, eord, roff, asrc, adst, eval, inv);
    aggregate_k<<<Nn, 128>>>(src, eord, roff, eval, inv, fz, buf);

    // 3) GAT layer 2
    gemm(buf, HDd, Bf2, 1024, fz, 1024, biasf2, Nn, 1024, HDd, 0);
    attn8_k<<<Nn, 256>>>(buf, watt2, asrc, adst);
    softmax_k<<<Nn, 128>>>(src, eord, roff, asrc, adst, eval, inv);
    aggregate_k<<<Nn, 128>>>(src, eord, roff, eval, inv, fz, h0);

    // 4) embedding = relu(h2 @ agg_w + agg_b) -> output (exact) + rounded copy
    gemm(h0, HDd, agg_w_r, HIDd, out_emb, HIDd, agg_b, Nn, HIDd, HDd, 1, 0, 0, embr);

    // 5) decoders (rounded outputs feed recon GEMMs)
    gemm(embr, HIDd, dr_w_r, EMBd, xs,              EMBd, dr_b, Nn, EMBd, HIDd, 0, 0, 1);
    gemm(embr, HIDd, dp_w_r, EMBd, xs + Nn * EMBd,  EMBd, dp_b, Nn, EMBd, HIDd, 0, 0, 1);

    // 6) reconstructions
    gemm(xs,             EMBd, rr_w_r, RNAd,  out_rna,  RNAd,  rr_b, Nn, RNAd,  EMBd, 0);
    gemm(xs + Nn * EMBd, EMBd, rp_w_r, PROTd, out_prot, PROTd, rp_b, Nn, PROTd, EMBd, 0);
}

// round 9
// speedup vs baseline: 3.6570x; 1.0638x over previous
#include <cuda_runtime.h>
#include <math.h>
#include <stdint.h>

// Problem constants
#define Nn    20000
#define Ee    320000
#define RNAd  2000
#define PROTd 100
#define EMBd  256
#define HIDd  128
#define NH    4
#define HDd   512
#define INWd  2100

// ---------------- scratch (device globals: allocation-free) ----------------
__device__ float    g_h0  [(size_t)Nn * HDd];    // layer activations
__device__ float    g_xs  [(size_t)Nn * HDd];    // decoder output [Nn,512]
__device__ float    g_buf [(size_t)Nn * HDd];    // layer activations
__device__ float    g_fz  [(size_t)Nn * 1024];   // fused GEMM out: [xs | residual]
__device__ float    g_asrc[Nn * NH];
__device__ float    g_adst[Nn * NH];
__device__ float    g_wr  [3000000];             // rounded/packed weight arena
__device__ float    g_embr[(size_t)Nn * HIDd];   // rounded embedding for decoders
__device__ int      g_deg [Nn];
__device__ int      g_cur [Nn];
__device__ int      g_roff[Nn + 1];
__device__ int      g_eord[Ee];

__device__ __forceinline__ float f2tf32(float x) {
    uint32_t u;
    asm("cvt.rna.tf32.f32 %0, %1;" : "=r"(u) : "f"(x));
    return __uint_as_float(u);
}

__device__ __forceinline__ void mma_tf32(float* d, const uint32_t* a, const uint32_t* b) {
    asm volatile(
        "mma.sync.aligned.m16n8k8.row.col.f32.tf32.tf32.f32 "
        "{%0,%1,%2,%3}, {%4,%5,%6,%7}, {%8,%9}, {%0,%1,%2,%3};"
        : "+f"(d[0]), "+f"(d[1]), "+f"(d[2]), "+f"(d[3])
        : "r"(a[0]), "r"(a[1]), "r"(a[2]), "r"(a[3]), "r"(b[0]), "r"(b[1]));
}

// ============================================================================
// prep_k: single launch doing all weight rounding / packing / bias concat.
// mode 0: d[i] = tf32(s1[i])
// mode 1: horizontal pack [s1|s2] rounded; row width w1+w2
// mode 2: fused-layer bias: d[i] = (i<w1) ? 0 : s1[i-w1]+s2[i-w1]
// mode 3: bias concat: d[i] = (i<w1) ? s1[i] : s2[i-w1]
// ============================================================================
struct Job { const float* s1; const float* s2; float* d; int n; int w1; int w2; int mode; };
struct Jobs { Job j[12]; int cnt; };

__global__ void prep_k(Jobs jobs)
{
    int t = blockIdx.y;
    if (t >= jobs.cnt) return;
    Job jb = jobs.j[t];
    int stride = gridDim.x * blockDim.x;
    for (int i = blockIdx.x * blockDim.x + threadIdx.x; i < jb.n; i += stride) {
        if (jb.mode == 0) {
            jb.d[i] = f2tf32(jb.s1[i]);
        } else if (jb.mode == 1) {
            int w = jb.w1 + jb.w2;
            int k = i / w, c = i - k * w;
            float v = (c < jb.w1) ? jb.s1[(size_t)k * jb.w1 + c]
                                  : jb.s2[(size_t)k * jb.w2 + (c - jb.w1)];
            jb.d[i] = f2tf32(v);
        } else if (jb.mode == 2) {
            jb.d[i] = (i < jb.w1) ? 0.f : (jb.s1[i - jb.w1] + jb.s2[i - jb.w1]);
        } else {
            jb.d[i] = (i < jb.w1) ? jb.s1[i] : jb.s2[i - jb.w1];
        }
    }
}

// ---------------- Wattn (both layers): 16 blocks; c<8 layer1, c>=8 layer2 ---
__global__ void wattn2_k(const float* __restrict__ ws1, const float* __restrict__ wd1,
                         const float* __restrict__ as1, const float* __restrict__ ad1,
                         const float* __restrict__ ws2, const float* __restrict__ wd2,
                         const float* __restrict__ as2, const float* __restrict__ ad2,
                         float* __restrict__ w1, float* __restrict__ w2)
{
    int c = blockIdx.x;
    int layer = c >> 3;
    int cc = c & 7;
    int t = threadIdx.x;
    const float* ws = layer ? ws2 : ws1;
    const float* wd = layer ? wd2 : wd1;
    const float* a_s = layer ? as2 : as1;
    const float* a_d = layer ? ad2 : ad1;
    float* wo = layer ? w2 : w1;
    const float* w = (cc < 4) ? ws : wd;
    int hh = (cc < 4) ? cc : (cc - 4);
    const float* a = (cc < 4) ? (a_s + hh * HIDd) : (a_d + hh * HIDd);
    #pragma unroll
    for (int kq = 0; kq < 4; kq++) {
        int k = t + kq * 128;
        float s = 0.f;
        const float* wr = w + (size_t)k * HDd + hh * HIDd;
        for (int d = 0; d < HIDd; d++) s += wr[d] * a[d];
        wo[cc * HDd + k] = s;
    }
}

// ---------------- attn coefs from h directly: 8 warps = 8 outputs ----------
__global__ __launch_bounds__(256) void attn8_k(
    const float* __restrict__ h, const float* __restrict__ wattn,
    float* __restrict__ asrc, float* __restrict__ adst)
{
    int n    = blockIdx.x;
    int c    = threadIdx.x >> 5;
    int lane = threadIdx.x & 31;
    const float4* hp = reinterpret_cast<const float4*>(h + (size_t)n * HDd);
    const float4* wp = reinterpret_cast<const float4*>(wattn + c * HDd);
    float s = 0.f;
    #pragma unroll
    for (int q = 0; q < 4; q++) {
        float4 a = hp[lane + q * 32];
        float4 b = wp[lane + q * 32];
        s += a.x * b.x + a.y * b.y + a.z * b.z + a.w * b.w;
    }
    #pragma unroll
    for (int o = 16; o; o >>= 1) s += __shfl_xor_sync(0xffffffffu, s, o);
    if (lane == 0) {
        if (c < 4) asrc[n * NH + c]       = s;
        else       adst[n * NH + (c - 4)] = s;
    }
}

// ============================================================================
// TF32 mma.sync GEMM. Block tile 128x128x16, 8 warps, warp tile 64x32.
// ============================================================================
#define ABUF 2048
#define BBUF 2112

__global__ __launch_bounds__(256, 2) void mma_gemm_k(
    const float* __restrict__ A, int lda,
    const float* __restrict__ B, int ldb,
    float* __restrict__ C, int ldc,
    const float* __restrict__ bias1,
    int M, int N, int K, int act, int round_a, int round_c, float* __restrict__ Cr)
{
    __shared__ float As[2 * ABUF];
    __shared__ float Bs[2 * BBUF];

    const int tid  = threadIdx.x;
    const int lane = tid & 31;
    const int warp = tid >> 5;
    const int wm   = warp >> 2;
    const int wn   = warp & 3;
    const int bm   = blockIdx.y * 128;
    const int bn   = blockIdx.x * 128;

    const int arow0 = tid >> 2;
    const int aj    = tid & 3;
    const int bc0 = tid >> 7;
    const int bnn = tid & 127;

    float a_reg[2][4], b_reg[2][4];
    float acc[4][4][4];
    #pragma unroll
    for (int i = 0; i < 4; i++)
        #pragma unroll
        for (int j = 0; j < 4; j++)
            #pragma unroll
            for (int r = 0; r < 4; r++) acc[i][j][r] = 0.f;

    const int KT = (K + 15) >> 4;

    {
        #pragma unroll
        for (int it = 0; it < 2; it++) {
            int row = arow0 + it * 64;
            bool rok = (bm + row) < M;
            const float* ap = A + (size_t)(bm + row) * lda;
            #pragma unroll
            for (int s = 0; s < 4; s++) {
                int kc = aj + 4 * s;
                a_reg[it][s] = (rok && kc < K) ? __ldg(ap + kc) : 0.f;
            }
            int c = bc0 + it * 2;
            bool nok = (bn + bnn) < N;
            #pragma unroll
            for (int s = 0; s < 4; s++) {
                int kc = c + 4 * s;
                b_reg[it][s] = (nok && kc < K) ? __ldg(B + (size_t)kc * ldb + bn + bnn) : 0.f;
            }
        }
    }

    for (int t = 0; t < KT; t++) {
        const int buf = t & 1;

        #pragma unroll
        for (int it = 0; it < 2; it++) {
            int row = arow0 + it * 64;
            int mt  = row >> 4;
            int rb  = (row >> 3) & 1;
            int lf  = ((row & 7) << 2) | aj;
            float2* d0 = (float2*)&As[buf * ABUF + (((0 * 2 + rb) * 8 + mt) * 32 + lf) * 2];
            float2* d1 = (float2*)&As[buf * ABUF + (((1 * 2 + rb) * 8 + mt) * 32 + lf) * 2];
            if (round_a) {
                *d0 = make_float2(f2tf32(a_reg[it][0]), f2tf32(a_reg[it][1]));
                *d1 = make_float2(f2tf32(a_reg[it][2]), f2tf32(a_reg[it][3]));
            } else {
                *d0 = make_float2(a_reg[it][0], a_reg[it][1]);
                *d1 = make_float2(a_reg[it][2], a_reg[it][3]);
            }

            int c  = bc0 + it * 2;
            int nt = bnn >> 3;
            int lb = ((bnn & 7) << 2) | c;
            float2* e0 = (float2*)&Bs[buf * BBUF + 0 * 1056 + nt * 66 + lb * 2];
            float2* e1 = (float2*)&Bs[buf * BBUF + 1 * 1056 + nt * 66 + lb * 2];
            *e0 = make_float2(b_reg[it][0], b_reg[it][1]);
            *e1 = make_float2(b_reg[it][2], b_reg[it][3]);
        }
        __syncthreads();

        if (t + 1 < KT) {
            const int k0 = (t + 1) << 4;
            #pragma unroll
            for (int it = 0; it < 2; it++) {
                int row = arow0 + it * 64;
                bool rok = (bm + row) < M;
                const float* ap = A + (size_t)(bm + row) * lda + k0;
                #pragma unroll
                for (int s = 0; s < 4; s++) {
                    int kc = aj + 4 * s;
                    a_reg[it][s] = (rok && (k0 + kc) < K) ? __ldg(ap + kc) : 0.f;
                }
                int c = bc0 + it * 2;
                bool nok = (bn + bnn) < N;
                #pragma unroll
                for (int s = 0; s < 4; s++) {
                    int kc = c + 4 * s;
                    b_reg[it][s] = (nok && (k0 + kc) < K) ? __ldg(B + (size_t)(k0 + kc) * ldb + bn + bnn) : 0.f;
                }
            }
        }

        #pragma unroll
        for (int ks = 0; ks < 2; ks++) {
            uint32_t af[4][4];
            #pragma unroll
            for (int i = 0; i < 4; i++) {
                int mt = wm * 4 + i;
                float2 p0 = *(float2*)&As[buf * ABUF + ((ks * 2 + 0) * 8 + mt) * 64 + lane * 2];
                float2 p1 = *(float2*)&As[buf * ABUF + ((ks * 2 + 1) * 8 + mt) * 64 + lane * 2];
                af[i][0] = __float_as_uint(p0.x);
                af[i][2] = __float_as_uint(p0.y);
                af[i][1] = __float_as_uint(p1.x);
                af[i][3] = __float_as_uint(p1.y);
            }
            uint32_t bf[4][2];
            #pragma unroll
            for (int j = 0; j < 4; j++) {
                int nt = wn * 4 + j;
                float2 q = *(float2*)&Bs[buf * BBUF + ks * 1056 + nt * 66 + lane * 2];
                bf[j][0] = __float_as_uint(q.x);
                bf[j][1] = __float_as_uint(q.y);
            }
            #pragma unroll
            for (int i = 0; i < 4; i++)
                #pragma unroll
                for (int j = 0; j < 4; j++)
                    mma_tf32(acc[i][j], af[i], bf[j]);
        }
        __syncthreads();
    }

    // ---- epilogue ----
    #pragma unroll
    for (int i = 0; i < 4; i++) {
        int row0 = bm + wm * 64 + i * 16 + (lane >> 2);
        #pragma unroll
        for (int j = 0; j < 4; j++) {
            int col0 = bn + wn * 32 + j * 8 + ((lane & 3) << 1);
            float bv0 = 0.f, bv1 = 0.f;
            if (bias1) {
                if (col0 < N)     bv0 = bias1[col0];
                if (col0 + 1 < N) bv1 = bias1[col0 + 1];
            }
            #pragma unroll
            for (int h = 0; h < 2; h++) {
                int row = row0 + 8 * h;
                if (row >= M) continue;
                float v0 = acc[i][j][2 * h + 0] + bv0;
                float v1 = acc[i][j][2 * h + 1] + bv1;
                if (act) { v0 = fmaxf(v0, 0.f); v1 = fmaxf(v1, 0.f); }
                float w0 = round_c ? f2tf32(v0) : v0;
                float w1 = round_c ? f2tf32(v1) : v1;
                float* cp = C + (size_t)row * ldc + col0;
                if (col0 + 1 < N) {
                    *(float2*)cp = make_float2(w0, w1);
                    if (Cr) *(float2*)(Cr + (size_t)row * ldc + col0) =
                                make_float2(f2tf32(v0), f2tf32(v1));
                } else if (col0 < N) {
                    *cp = w0;
                    if (Cr) Cr[(size_t)row * ldc + col0] = f2tf32(v0);
                }
            }
        }
    }
}

// ---------------- CSR build (once per launch) ----------------
__global__ void zero_deg_k(int* __restrict__ deg)
{
    int i = blockIdx.x * blockDim.x + threadIdx.x;
    if (i < Nn) deg[i] = 0;
}

__global__ void hist_k(const int* __restrict__ dst, int* __restrict__ deg)
{
    int e = blockIdx.x * blockDim.x + threadIdx.x;
    if (e < Ee) atomicAdd(&deg[dst[e]], 1);
}

#define SCAN_T 1024
#define SCAN_C 20
__global__ __launch_bounds__(SCAN_T) void scan_k(const int* __restrict__ deg,
                                                 int* __restrict__ roff,
                                                 int* __restrict__ cur)
{
    __shared__ int ss[SCAN_T];
    int t = threadIdx.x;
    int base = t * SCAN_C;
    int loc[SCAN_C];
    int sum = 0;
    #pragma unroll
    for (int i = 0; i < SCAN_C; i++) {
        int idx = base + i;
        int v = (idx < Nn) ? deg[idx] : 0;
        loc[i] = sum;
        sum += v;
    }
    ss[t] = sum;
    __syncthreads();
    int own = sum;
    for (int off = 1; off < SCAN_T; off <<= 1) {
        int v = (t >= off) ? ss[t - off] : 0;
        __syncthreads();
        ss[t] += v;
        __syncthreads();
    }
    int excl = ss[t] - own;
    #pragma unroll
    for (int i = 0; i < SCAN_C; i++) {
        int idx = base + i;
        if (idx < Nn) { roff[idx] = excl + loc[i]; cur[idx] = excl + loc[i]; }
    }
    if (t == SCAN_T - 1) roff[Nn] = ss[SCAN_T - 1];
}

__global__ void bucket_k(const int* __restrict__ dst, int* __restrict__ cur,
                         int* __restrict__ eord)
{
    int e = blockIdx.x * blockDim.x + threadIdx.x;
    if (e < Ee) {
        int pos = atomicAdd(&cur[dst[e]], 1);
        eord[pos] = e;
    }
}

// ============================================================================
// Fused segment softmax + gather-aggregate + residual + ReLU + tf32 round.
// Block = dst node, 4 warps = 4 heads; lane covers 4 feats (float4).
// Pass 1: lane-parallel segment max. Pass 2: per-edge exp (uniform) fused
// with the alpha-weighted message gather; normalize once at the end.
// ============================================================================
__global__ __launch_bounds__(128) void agg_fused_k(
    const int* __restrict__ src, const int* __restrict__ eord,
    const int* __restrict__ roff,
    const float* __restrict__ asrc, const float* __restrict__ adst,
    const float* __restrict__ fz, float* __restrict__ out)
{
    int n    = blockIdx.x;
    int h    = threadIdx.x >> 5;
    int lane = threadIdx.x & 31;
    int r0 = roff[n], r1 = roff[n + 1];
    float adn = adst[n * NH + h];

    // pass 1: segment max (lanes stride edges)
    float m = -3.4e38f;
    for (int j = r0 + lane; j < r1; j += 32) {
        int eid = __ldg(eord + j);
        float v = __ldg(asrc + __ldg(src + eid) * NH + h) + adn;
        v = v > 0.f ? v : 0.2f * v;
        m = fmaxf(m, v);
    }
    #pragma unroll
    for (int o = 16; o; o >>= 1) m = fmaxf(m, __shfl_xor_sync(0xffffffffu, m, o));

    // pass 2: exp + weighted gather in one sweep
    float s = 0.f;
    float4 acc = make_float4(0.f, 0.f, 0.f, 0.f);
    for (int j = r0; j < r1; j++) {
        int eid = __ldg(eord + j);
        int sn  = __ldg(src + eid);
        float v = __ldg(asrc + sn * NH + h) + adn;
        v = v > 0.f ? v : 0.2f * v;
        float ex = __expf(v - m);
        s += ex;
        float4 vv = *reinterpret_cast<const float4*>(fz + (size_t)sn * 1024 + h * HIDd + lane * 4);
        acc.x += ex * vv.x; acc.y += ex * vv.y;
        acc.z += ex * vv.z; acc.w += ex * vv.w;
    }
    float iv = (r1 > r0) ? 1.f / (s + 1e-16f) : 0.f;

    float4 r = *reinterpret_cast<const float4*>(fz + (size_t)n * 1024 + 512 + h * HIDd + lane * 4);
    float4 o;
    o.x = f2tf32(fmaxf(r.x + acc.x * iv, 0.f));
    o.y = f2tf32(fmaxf(r.y + acc.y * iv, 0.f));
    o.z = f2tf32(fmaxf(r.z + acc.z * iv, 0.f));
    o.w = f2tf32(fmaxf(r.w + acc.w * iv, 0.f));
    *reinterpret_cast<float4*>(out + (size_t)n * HDd + h * HIDd + lane * 4) = o;
}

// ---------------- host helpers ----------------
static inline void gemm(const float* A, int lda, const float* B, int ldb,
                        float* C, int ldc, const float* b1,
                        int M, int N, int K, int act,
                        int round_a = 0, int round_c = 0, float* Cr = nullptr)
{
    dim3 grid((N + 127) / 128, (M + 127) / 128);
    mma_gemm_k<<<grid, 256>>>(A, lda, B, ldb, C, ldc, b1, M, N, K, act, round_a, round_c, Cr);
}

extern "C" void kernel_launch(void* const* d_in, const int* in_sizes, int n_in,
                              void* d_out, int out_size)
{
    const float* x      = (const float*)d_in[0];
    const int*   ei     = (const int*)  d_in[1];
    const float* W_rna  = (const float*)d_in[2];
    const float* b_rna  = (const float*)d_in[3];
    const float* W_prot = (const float*)d_in[4];
    const float* b_prot = (const float*)d_in[5];
    const float* g1_ws  = (const float*)d_in[6];
    const float* g1_wd  = (const float*)d_in[7];
    const float* g1_as  = (const float*)d_in[8];
    const float* g1_ad  = (const float*)d_in[9];
    const float* g1_b   = (const float*)d_in[10];
    const float* l1_w   = (const float*)d_in[11];
    const float* l1_b   = (const float*)d_in[12];
    const float* g2_ws  = (const float*)d_in[13];
    const float* g2_wd  = (const float*)d_in[14];
    const float* g2_as  = (const float*)d_in[15];
    const float* g2_ad  = (const float*)d_in[16];
    const float* g2_b   = (const float*)d_in[17];
    const float* l2_w   = (const float*)d_in[18];
    const float* l2_b   = (const float*)d_in[19];
    const float* agg_w  = (const float*)d_in[20];
    const float* agg_b  = (const float*)d_in[21];
    const float* dr_w   = (const float*)d_in[22];
    const float* dr_b   = (const float*)d_in[23];
    const float* dp_w   = (const float*)d_in[24];
    const float* dp_b   = (const float*)d_in[25];
    const float* rr_w   = (const float*)d_in[26];
    const float* rr_b   = (const float*)d_in[27];
    const float* rp_w   = (const float*)d_in[28];
    const float* rp_b   = (const float*)d_in[29];

    const int* src = ei;
    const int* dst = ei + Ee;

    float* out = (float*)d_out;
    float* out_rna  = out;                                     // [Nn, 2000]
    float* out_prot = out + (size_t)Nn * RNAd;                 // [Nn, 100]
    float* out_emb  = out + (size_t)Nn * (RNAd + PROTd);       // [Nn, 128]

    float *h0, *xs, *buf, *fz, *asrc, *adst, *wr, *embr;
    int *deg, *cur, *roff, *eord;
    cudaGetSymbolAddress((void**)&h0,   g_h0);
    cudaGetSymbolAddress((void**)&xs,   g_xs);
    cudaGetSymbolAddress((void**)&buf,  g_buf);
    cudaGetSymbolAddress((void**)&fz,   g_fz);
    cudaGetSymbolAddress((void**)&asrc, g_asrc);
    cudaGetSymbolAddress((void**)&adst, g_adst);
    cudaGetSymbolAddress((void**)&wr,   g_wr);
    cudaGetSymbolAddress((void**)&embr, g_embr);
    cudaGetSymbolAddress((void**)&deg,  g_deg);
    cudaGetSymbolAddress((void**)&cur,  g_cur);
    cudaGetSymbolAddress((void**)&roff, g_roff);
    cudaGetSymbolAddress((void**)&eord, g_eord);

    // ---- weight arena ----
    size_t wo = 0;
    auto arena = [&](size_t n) -> float* { float* p = wr + wo; wo += n; return p; };
    float* W_rna_r  = arena((size_t)RNAd * EMBd);
    float* W_prot_r = arena((size_t)PROTd * EMBd);
    float* agg_w_r  = arena((size_t)HDd * HIDd);
    float* rr_w_r   = arena((size_t)EMBd * RNAd);
    float* rp_w_r   = arena((size_t)EMBd * PROTd);
    float* Bf1      = arena((size_t)512 * 1024);
    float* Bf2      = arena((size_t)512 * 1024);
    float* Bdec     = arena((size_t)128 * 512);
    float* biasf1   = arena(1024);
    float* biasf2   = arena(1024);
    float* bdec     = arena(512);
    float* watt1    = arena(8 * 512);
    float* watt2    = arena(8 * 512);

    // ---- single prep launch: round / pack / bias ----
    Jobs jobs;
    int jc = 0;
    auto addj = [&](const float* s1, const float* s2, float* d, int n, int w1, int w2, int mode) {
        jobs.j[jc++] = Job{s1, s2, d, n, w1, w2, mode};
    };
    addj(W_rna,  nullptr, W_rna_r,  RNAd * EMBd,  0, 0, 0);
    addj(W_prot, nullptr, W_prot_r, PROTd * EMBd, 0, 0, 0);
    addj(agg_w,  nullptr, agg_w_r,  HDd * HIDd,   0, 0, 0);
    addj(rr_w,   nullptr, rr_w_r,   EMBd * RNAd,  0, 0, 0);
    addj(rp_w,   nullptr, rp_w_r,   EMBd * PROTd, 0, 0, 0);
    addj(g1_ws, l1_w, Bf1, 512 * 1024, 512, 512, 1);
    addj(g2_ws, l2_w, Bf2, 512 * 1024, 512, 512, 1);
    addj(dr_w,  dp_w, Bdec, 128 * 512, 256, 256, 1);
    addj(g1_b,  l1_b, biasf1, 1024, 512, 0, 2);
    addj(g2_b,  l2_b, biasf2, 1024, 512, 0, 2);
    addj(dr_b,  dp_b, bdec,   512,  256, 0, 3);
    jobs.cnt = jc;
    prep_k<<<dim3(64, jc), 256>>>(jobs);

    wattn2_k<<<16, 128>>>(g1_ws, g1_wd, g1_as, g1_ad,
                          g2_ws, g2_wd, g2_as, g2_ad, watt1, watt2);

    // ---- CSR build (dst-sorted edge order) ----
    zero_deg_k<<<(Nn + 255) / 256, 256>>>(deg);
    hist_k<<<(Ee + 255) / 256, 256>>>(dst, deg);
    scan_k<<<1, SCAN_T>>>(deg, roff, cur);
    bucket_k<<<(Ee + 255) / 256, 256>>>(dst, cur, eord);

    // 1) input embeddings (A=x raw f32, rounded in-kernel)
    gemm(x,        INWd, W_rna_r,  EMBd, h0,        HDd, b_rna,  Nn, EMBd, RNAd,  0, 1, 1);
    gemm(x + RNAd, INWd, W_prot_r, EMBd, h0 + EMBd, HDd, b_prot, Nn, EMBd, PROTd, 0, 1, 1);

    // 2) GAT layer 1
    gemm(h0, HDd, Bf1, 1024, fz, 1024, biasf1, Nn, 1024, HDd, 0);
    attn8_k<<<Nn, 256>>>(h0, watt1, asrc, adst);
    agg_fused_k<<<Nn, 128>>>(src, eord, roff, asrc, adst, fz, buf);

    // 3) GAT layer 2
    gemm(buf, HDd, Bf2, 1024, fz, 1024, biasf2, Nn, 1024, HDd, 0);
    attn8_k<<<Nn, 256>>>(buf, watt2, asrc, adst);
    agg_fused_k<<<Nn, 128>>>(src, eord, roff, asrc, adst, fz, h0);

    // 4) embedding = relu(h2 @ agg_w + agg_b) -> output (exact) + rounded copy
    gemm(h0, HDd, agg_w_r, HIDd, out_emb, HIDd, agg_b, Nn, HIDd, HDd, 1, 0, 0, embr);

    // 5) packed decoders: xs[:, :256]=rna_d, xs[:, 256:]=prot_d (rounded)
    gemm(embr, HIDd, Bdec, 512, xs, 512, bdec, Nn, 512, HIDd, 0, 0, 1);

    // 6) reconstructions (A = xs at lda=512, offsets 0 / 256)
    gemm(xs,       512, rr_w_r, RNAd,  out_rna,  RNAd,  rr_b, Nn, RNAd,  EMBd, 0);
    gemm(xs + 256, 512, rp_w_r, PROTd, out_prot, PROTd, rp_b, Nn, PROTd, EMBd, 0);
}

// round 10
// speedup vs baseline: 4.7899x; 1.3098x over previous
#include <cuda_runtime.h>
#include <cuda_fp16.h>
#include <math.h>
#include <stdint.h>

// Problem constants
#define Nn    20000
#define Ee    320000
#define RNAd  2000
#define PROTd 100
#define EMBd  256
#define HIDd  128
#define NH    4
#define HDd   512
#define INWd  2100

// ---------------- scratch (device globals: allocation-free) ----------------
__device__ float    g_h0  [(size_t)Nn * HDd];    // layer activations
__device__ float    g_xs  [(size_t)Nn * HDd];    // decoder output [Nn,512]
__device__ float    g_buf [(size_t)Nn * HDd];    // layer activations
__device__ float    g_fz  [(size_t)Nn * 1024];   // fused GEMM out: [xs | residual]
__device__ float    g_asrc[Nn * NH];
__device__ float    g_adst[Nn * NH];
__device__ float    g_wr  [1200000];             // packed weight arena
__device__ int      g_deg [Nn];
__device__ int      g_cur [Nn];
__device__ int      g_roff[Nn + 1];
__device__ int      g_eord[Ee];

// ============================================================================
// prep_k: single launch doing all weight packing / bias concat (f32, no round)
// mode 1: horizontal pack [s1|s2]; row width w1+w2
// mode 2: fused-layer bias: d[i] = (i<w1) ? 0 : s1[i-w1]+s2[i-w1]
// mode 3: bias concat: d[i] = (i<w1) ? s1[i] : s2[i-w1]
// ============================================================================
struct Job { const float* s1; const float* s2; float* d; int n; int w1; int w2; int mode; };
struct Jobs { Job j[12]; int cnt; };

__global__ void prep_k(Jobs jobs)
{
    int t = blockIdx.y;
    if (t >= jobs.cnt) return;
    Job jb = jobs.j[t];
    int stride = gridDim.x * blockDim.x;
    for (int i = blockIdx.x * blockDim.x + threadIdx.x; i < jb.n; i += stride) {
        if (jb.mode == 1) {
            int w = jb.w1 + jb.w2;
            int k = i / w, c = i - k * w;
            jb.d[i] = (c < jb.w1) ? jb.s1[(size_t)k * jb.w1 + c]
                                  : jb.s2[(size_t)k * jb.w2 + (c - jb.w1)];
        } else if (jb.mode == 2) {
            jb.d[i] = (i < jb.w1) ? 0.f : (jb.s1[i - jb.w1] + jb.s2[i - jb.w1]);
        } else {
            jb.d[i] = (i < jb.w1) ? jb.s1[i] : jb.s2[i - jb.w1];
        }
    }
}

// ---------------- Wattn (both layers): 16 blocks; c<8 layer1, c>=8 layer2 ---
__global__ void wattn2_k(const float* __restrict__ ws1, const float* __restrict__ wd1,
                         const float* __restrict__ as1, const float* __restrict__ ad1,
                         const float* __restrict__ ws2, const float* __restrict__ wd2,
                         const float* __restrict__ as2, const float* __restrict__ ad2,
                         float* __restrict__ w1, float* __restrict__ w2)
{
    int c = blockIdx.x;
    int layer = c >> 3;
    int cc = c & 7;
    int t = threadIdx.x;
    const float* ws = layer ? ws2 : ws1;
    const float* wd = layer ? wd2 : wd1;
    const float* a_s = layer ? as2 : as1;
    const float* a_d = layer ? ad2 : ad1;
    float* wo = layer ? w2 : w1;
    const float* w = (cc < 4) ? ws : wd;
    int hh = (cc < 4) ? cc : (cc - 4);
    const float* a = (cc < 4) ? (a_s + hh * HIDd) : (a_d + hh * HIDd);
    #pragma unroll
    for (int kq = 0; kq < 4; kq++) {
        int k = t + kq * 128;
        float s = 0.f;
        const float* wr = w + (size_t)k * HDd + hh * HIDd;
        for (int d = 0; d < HIDd; d++) s += wr[d] * a[d];
        wo[cc * HDd + k] = s;
    }
}

// ---------------- attn coefs from h directly: 8 warps = 8 outputs ----------
__global__ __launch_bounds__(256) void attn8_k(
    const float* __restrict__ h, const float* __restrict__ wattn,
    float* __restrict__ asrc, float* __restrict__ adst)
{
    int n    = blockIdx.x;
    int c    = threadIdx.x >> 5;
    int lane = threadIdx.x & 31;
    const float4* hp = reinterpret_cast<const float4*>(h + (size_t)n * HDd);
    const float4* wp = reinterpret_cast<const float4*>(wattn + c * HDd);
    float s = 0.f;
    #pragma unroll
    for (int q = 0; q < 4; q++) {
        float4 a = hp[lane + q * 32];
        float4 b = wp[lane + q * 32];
        s += a.x * b.x + a.y * b.y + a.z * b.z + a.w * b.w;
    }
    #pragma unroll
    for (int o = 16; o; o >>= 1) s += __shfl_xor_sync(0xffffffffu, s, o);
    if (lane == 0) {
        if (c < 4) asrc[n * NH + c]       = s;
        else       adst[n * NH + (c - 4)] = s;
    }
}

// ============================================================================
// FP16 mma.sync GEMM (f32 in gmem, converted to fp16 at smem store; f32 accum).
// Block tile 128x128x16, 8 warps, warp tile 64x32, mma.m16n8k16.
// Smem fragment-order layouts (all conflict-free):
//   A: [mt(8)][q(4)][lane(32)] half2 ; q = (rowhalf) + 2*(kseg)
//   B: [q(2)][nt(16)][lane(32)] half2 ; q = kseg
// Loaders: one STS.128 per thread per tile per operand.
// ============================================================================
__device__ __forceinline__ void mma_f16(float* d, const uint32_t* a, const uint32_t* b) {
    asm volatile(
        "mma.sync.aligned.m16n8k16.row.col.f32.f16.f16.f32 "
        "{%0,%1,%2,%3}, {%4,%5,%6,%7}, {%8,%9}, {%0,%1,%2,%3};"
        : "+f"(d[0]), "+f"(d[1]), "+f"(d[2]), "+f"(d[3])
        : "r"(a[0]), "r"(a[1]), "r"(a[2]), "r"(a[3]), "r"(b[0]), "r"(b[1]));
}

__global__ __launch_bounds__(256, 2) void mma_gemm_k(
    const float* __restrict__ A, int lda,
    const float* __restrict__ B, int ldb,
    float* __restrict__ C, int ldc,
    const float* __restrict__ bias1,
    int M, int N, int K, int act)
{
    __shared__ __align__(16) half2 Ash[2][1024];
    __shared__ __align__(16) half2 Bsh[2][1024];

    const int tid  = threadIdx.x;
    const int lane = tid & 31;
    const int warp = tid >> 5;
    const int wm   = warp >> 2;    // 0..1
    const int wn   = warp & 3;     // 0..3
    const int bm   = blockIdx.y * 128;
    const int bn   = blockIdx.x * 128;

    // A loader: row = tid>>1 (0..127), kseg = tid&1 (8 floats)
    const int arow = tid >> 1;
    const int asg  = tid & 1;
    const bool rok = (bm + arow) < M;
    const float* Arow = A + (size_t)(bm + arow) * lda;
    const int a_mt = arow >> 4;
    const int a_q  = ((arow >> 3) & 1) + 2 * asg;
    const int a_sl = (a_mt * 4 + a_q) * 32 + (arow & 7) * 4;   // half2 index

    // B loader: n = tid&127, kseg = tid>>7 (8 k values, strided by ldb)
    const int bnn = tid & 127;
    const int bq  = tid >> 7;
    const bool nok = (bn + bnn) < N;
    const int b_nt = bnn >> 3;
    const int b_sl = (bq * 16 + b_nt) * 32 + (bnn & 7) * 4;    // half2 index

    float a8[8], b8[8];
    float acc[4][4][4];
    #pragma unroll
    for (int i = 0; i < 4; i++)
        #pragma unroll
        for (int j = 0; j < 4; j++)
            #pragma unroll
            for (int r = 0; r < 4; r++) acc[i][j][r] = 0.f;

    const int KT = (K + 15) >> 4;

    // ---- prologue: fetch tile 0 into regs ----
    {
        const int ka = asg * 8;
        if (rok && ka + 7 < K) {
            float4 v0 = *reinterpret_cast<const float4*>(Arow + ka);
            float4 v1 = *reinterpret_cast<const float4*>(Arow + ka + 4);
            a8[0]=v0.x; a8[1]=v0.y; a8[2]=v0.z; a8[3]=v0.w;
            a8[4]=v1.x; a8[5]=v1.y; a8[6]=v1.z; a8[7]=v1.w;
        } else {
            #pragma unroll
            for (int i = 0; i < 8; i++)
                a8[i] = (rok && ka + i < K) ? Arow[ka + i] : 0.f;
        }
        const int kb = bq * 8;
        #pragma unroll
        for (int i = 0; i < 8; i++)
            b8[i] = (nok && kb + i < K) ? __ldg(B + (size_t)(kb + i) * ldb + bn + bnn) : 0.f;
    }

    for (int t = 0; t < KT; t++) {
        const int buf = t & 1;

        // ---- pack + store tile t (one STS.128 each) ----
        {
            half2 ph[4];
            ph[0] = __floats2half2_rn(a8[0], a8[1]);
            ph[1] = __floats2half2_rn(a8[2], a8[3]);
            ph[2] = __floats2half2_rn(a8[4], a8[5]);
            ph[3] = __floats2half2_rn(a8[6], a8[7]);
            *reinterpret_cast<float4*>(&Ash[buf][a_sl]) = *reinterpret_cast<float4*>(ph);
            ph[0] = __floats2half2_rn(b8[0], b8[1]);
            ph[1] = __floats2half2_rn(b8[2], b8[3]);
            ph[2] = __floats2half2_rn(b8[4], b8[5]);
            ph[3] = __floats2half2_rn(b8[6], b8[7]);
            *reinterpret_cast<float4*>(&Bsh[buf][b_sl]) = *reinterpret_cast<float4*>(ph);
        }
        __syncthreads();

        // ---- prefetch tile t+1 ----
        if (t + 1 < KT) {
            const int ka = (t + 1) * 16 + asg * 8;
            if (rok && ka + 7 < K) {
                float4 v0 = *reinterpret_cast<const float4*>(Arow + ka);
                float4 v1 = *reinterpret_cast<const float4*>(Arow + ka + 4);
                a8[0]=v0.x; a8[1]=v0.y; a8[2]=v0.z; a8[3]=v0.w;
                a8[4]=v1.x; a8[5]=v1.y; a8[6]=v1.z; a8[7]=v1.w;
            } else {
                #pragma unroll
                for (int i = 0; i < 8; i++)
                    a8[i] = (rok && ka + i < K) ? Arow[ka + i] : 0.f;
            }
            const int kb = (t + 1) * 16 + bq * 8;
            if (kb + 7 < K) {
                #pragma unroll
                for (int i = 0; i < 8; i++)
                    b8[i] = nok ? __ldg(B + (size_t)(kb + i) * ldb + bn + bnn) : 0.f;
            } else {
                #pragma unroll
                for (int i = 0; i < 8; i++)
                    b8[i] = (nok && kb + i < K) ? __ldg(B + (size_t)(kb + i) * ldb + bn + bnn) : 0.f;
            }
        }

        // ---- compute from buffer ----
        const uint32_t* As32 = reinterpret_cast<const uint32_t*>(&Ash[buf][0]);
        const uint32_t* Bs32 = reinterpret_cast<const uint32_t*>(&Bsh[buf][0]);
        uint32_t af[4][4], bf[4][2];
        #pragma unroll
        for (int i = 0; i < 4; i++) {
            int mt = wm * 4 + i;
            #pragma unroll
            for (int q = 0; q < 4; q++)
                af[i][q] = As32[(mt * 4 + q) * 32 + lane];
        }
        #pragma unroll
        for (int j = 0; j < 4; j++) {
            int nt = wn * 4 + j;
            bf[j][0] = Bs32[nt * 32 + lane];
            bf[j][1] = Bs32[(16 + nt) * 32 + lane];
        }
        #pragma unroll
        for (int i = 0; i < 4; i++)
            #pragma unroll
            for (int j = 0; j < 4; j++)
                mma_f16(acc[i][j], af[i], bf[j]);
        __syncthreads();
    }

    // ---- epilogue ----
    #pragma unroll
    for (int i = 0; i < 4; i++) {
        int row0 = bm + wm * 64 + i * 16 + (lane >> 2);
        #pragma unroll
        for (int j = 0; j < 4; j++) {
            int col0 = bn + wn * 32 + j * 8 + ((lane & 3) << 1);
            float bv0 = 0.f, bv1 = 0.f;
            if (bias1) {
                if (col0 < N)     bv0 = bias1[col0];
                if (col0 + 1 < N) bv1 = bias1[col0 + 1];
            }
            #pragma unroll
            for (int h = 0; h < 2; h++) {
                int row = row0 + 8 * h;
                if (row >= M) continue;
                float v0 = acc[i][j][2 * h + 0] + bv0;
                float v1 = acc[i][j][2 * h + 1] + bv1;
                if (act) { v0 = fmaxf(v0, 0.f); v1 = fmaxf(v1, 0.f); }
                float* cp = C + (size_t)row * ldc + col0;
                if (col0 + 1 < N)  *(float2*)cp = make_float2(v0, v1);
                else if (col0 < N) *cp = v0;
            }
        }
    }
}

// ---------------- CSR build (once per launch) ----------------
__global__ void zero_deg_k(int* __restrict__ deg)
{
    int i = blockIdx.x * blockDim.x + threadIdx.x;
    if (i < Nn) deg[i] = 0;
}

__global__ void hist_k(const int* __restrict__ dst, int* __restrict__ deg)
{
    int e = blockIdx.x * blockDim.x + threadIdx.x;
    if (e < Ee) atomicAdd(&deg[dst[e]], 1);
}

#define SCAN_T 1024
#define SCAN_C 20
__global__ __launch_bounds__(SCAN_T) void scan_k(const int* __restrict__ deg,
                                                 int* __restrict__ roff,
                                                 int* __restrict__ cur)
{
    __shared__ int ss[SCAN_T];
    int t = threadIdx.x;
    int base = t * SCAN_C;
    int loc[SCAN_C];
    int sum = 0;
    #pragma unroll
    for (int i = 0; i < SCAN_C; i++) {
        int idx = base + i;
        int v = (idx < Nn) ? deg[idx] : 0;
        loc[i] = sum;
        sum += v;
    }
    ss[t] = sum;
    __syncthreads();
    int own = sum;
    for (int off = 1; off < SCAN_T; off <<= 1) {
        int v = (t >= off) ? ss[t - off] : 0;
        __syncthreads();
        ss[t] += v;
        __syncthreads();
    }
    int excl = ss[t] - own;
    #pragma unroll
    for (int i = 0; i < SCAN_C; i++) {
        int idx = base + i;
        if (idx < Nn) { roff[idx] = excl + loc[i]; cur[idx] = excl + loc[i]; }
    }
    if (t == SCAN_T - 1) roff[Nn] = ss[SCAN_T - 1];
}

__global__ void bucket_k(const int* __restrict__ dst, int* __restrict__ cur,
                         int* __restrict__ eord)
{
    int e = blockIdx.x * blockDim.x + threadIdx.x;
    if (e < Ee) {
        int pos = atomicAdd(&cur[dst[e]], 1);
        eord[pos] = e;
    }
}

// ============================================================================
// Fused segment softmax + gather-aggregate + residual + ReLU.
// Block = dst node, 4 warps = 4 heads; lane covers 4 feats (float4).
// ============================================================================
__global__ __launch_bounds__(128) void agg_fused_k(
    const int* __restrict__ src, const int* __restrict__ eord,
    const int* __restrict__ roff,
    const float* __restrict__ asrc, const float* __restrict__ adst,
    const float* __restrict__ fz, float* __restrict__ out)
{
    int n    = blockIdx.x;
    int h    = threadIdx.x >> 5;
    int lane = threadIdx.x & 31;
    int r0 = roff[n], r1 = roff[n + 1];
    float adn = adst[n * NH + h];

    // pass 1: segment max (lanes stride edges)
    float m = -3.4e38f;
    for (int j = r0 + lane; j < r1; j += 32) {
        int eid = __ldg(eord + j);
        float v = __ldg(asrc + __ldg(src + eid) * NH + h) + adn;
        v = v > 0.f ? v : 0.2f * v;
        m = fmaxf(m, v);
    }
    #pragma unroll
    for (int o = 16; o; o >>= 1) m = fmaxf(m, __shfl_xor_sync(0xffffffffu, m, o));

    // pass 2: exp + weighted gather in one sweep
    float s = 0.f;
    float4 acc = make_float4(0.f, 0.f, 0.f, 0.f);
    for (int j = r0; j < r1; j++) {
        int eid = __ldg(eord + j);
        int sn  = __ldg(src + eid);
        float v = __ldg(asrc + sn * NH + h) + adn;
        v = v > 0.f ? v : 0.2f * v;
        float ex = __expf(v - m);
        s += ex;
        float4 vv = *reinterpret_cast<const float4*>(fz + (size_t)sn * 1024 + h * HIDd + lane * 4);
        acc.x += ex * vv.x; acc.y += ex * vv.y;
        acc.z += ex * vv.z; acc.w += ex * vv.w;
    }
    float iv = (r1 > r0) ? 1.f / (s + 1e-16f) : 0.f;

    float4 r = *reinterpret_cast<const float4*>(fz + (size_t)n * 1024 + 512 + h * HIDd + lane * 4);
    float4 o;
    o.x = fmaxf(r.x + acc.x * iv, 0.f);
    o.y = fmaxf(r.y + acc.y * iv, 0.f);
    o.z = fmaxf(r.z + acc.z * iv, 0.f);
    o.w = fmaxf(r.w + acc.w * iv, 0.f);
    *reinterpret_cast<float4*>(out + (size_t)n * HDd + h * HIDd + lane * 4) = o;
}

// ---------------- host helpers ----------------
static inline void gemm(const float* A, int lda, const float* B, int ldb,
                        float* C, int ldc, const float* b1,
                        int M, int N, int K, int act)
{
    dim3 grid((N + 127) / 128, (M + 127) / 128);
    mma_gemm_k<<<grid, 256>>>(A, lda, B, ldb, C, ldc, b1, M, N, K, act);
}

extern "C" void kernel_launch(void* const* d_in, const int* in_sizes, int n_in,
                              void* d_out, int out_size)
{
    const float* x      = (const float*)d_in[0];
    const int*   ei     = (const int*)  d_in[1];
    const float* W_rna  = (const float*)d_in[2];
    const float* b_rna  = (const float*)d_in[3];
    const float* W_prot = (const float*)d_in[4];
    const float* b_prot = (const float*)d_in[5];
    const float* g1_ws  = (const float*)d_in[6];
    const float* g1_wd  = (const float*)d_in[7];
    const float* g1_as  = (const float*)d_in[8];
    const float* g1_ad  = (const float*)d_in[9];
    const float* g1_b   = (const float*)d_in[10];
    const float* l1_w   = (const float*)d_in[11];
    const float* l1_b   = (const float*)d_in[12];
    const float* g2_ws  = (const float*)d_in[13];
    const float* g2_wd  = (const float*)d_in[14];
    const float* g2_as  = (const float*)d_in[15];
    const float* g2_ad  = (const float*)d_in[16];
    const float* g2_b   = (const float*)d_in[17];
    const float* l2_w   = (const float*)d_in[18];
    const float* l2_b   = (const float*)d_in[19];
    const float* agg_w  = (const float*)d_in[20];
    const float* agg_b  = (const float*)d_in[21];
    const float* dr_w   = (const float*)d_in[22];
    const float* dr_b   = (const float*)d_in[23];
    const float* dp_w   = (const float*)d_in[24];
    const float* dp_b   = (const float*)d_in[25];
    const float* rr_w   = (const float*)d_in[26];
    const float* rr_b   = (const float*)d_in[27];
    const float* rp_w   = (const float*)d_in[28];
    const float* rp_b   = (const float*)d_in[29];

    const int* src = ei;
    const int* dst = ei + Ee;

    float* out = (float*)d_out;
    float* out_rna  = out;                                     // [Nn, 2000]
    float* out_prot = out + (size_t)Nn * RNAd;                 // [Nn, 100]
    float* out_emb  = out + (size_t)Nn * (RNAd + PROTd);       // [Nn, 128]

    float *h0, *xs, *buf, *fz, *asrc, *adst, *wr;
    int *deg, *cur, *roff, *eord;
    cudaGetSymbolAddress((void**)&h0,   g_h0);
    cudaGetSymbolAddress((void**)&xs,   g_xs);
    cudaGetSymbolAddress((void**)&buf,  g_buf);
    cudaGetSymbolAddress((void**)&fz,   g_fz);
    cudaGetSymbolAddress((void**)&asrc, g_asrc);
    cudaGetSymbolAddress((void**)&adst, g_adst);
    cudaGetSymbolAddress((void**)&wr,   g_wr);
    cudaGetSymbolAddress((void**)&deg,  g_deg);
    cudaGetSymbolAddress((void**)&cur,  g_cur);
    cudaGetSymbolAddress((void**)&roff, g_roff);
    cudaGetSymbolAddress((void**)&eord, g_eord);

    // ---- packed weight arena (f32; fp16 conversion happens in GEMM loader) ----
    size_t wo = 0;
    auto arena = [&](size_t n) -> float* { float* p = wr + wo; wo += n; return p; };
    float* Bf1    = arena((size_t)512 * 1024);
    float* Bf2    = arena((size_t)512 * 1024);
    float* Bdec   = arena((size_t)128 * 512);
    float* biasf1 = arena(1024);
    float* biasf2 = arena(1024);
    float* bdec   = arena(512);
    float* watt1  = arena(8 * 512);
    float* watt2  = arena(8 * 512);

    Jobs jobs;
    int jc = 0;
    auto addj = [&](const float* s1, const float* s2, float* d, int n, int w1, int w2, int mode) {
        jobs.j[jc++] = Job{s1, s2, d, n, w1, w2, mode};
    };
    addj(g1_ws, l1_w, Bf1, 512 * 1024, 512, 512, 1);
    addj(g2_ws, l2_w, Bf2, 512 * 1024, 512, 512, 1);
    addj(dr_w,  dp_w, Bdec, 128 * 512, 256, 256, 1);
    addj(g1_b,  l1_b, biasf1, 1024, 512, 0, 2);
    addj(g2_b,  l2_b, biasf2, 1024, 512, 0, 2);
    addj(dr_b,  dp_b, bdec,   512,  256, 0, 3);
    jobs.cnt = jc;
    prep_k<<<dim3(64, jc), 256>>>(jobs);

    wattn2_k<<<16, 128>>>(g1_ws, g1_wd, g1_as, g1_ad,
                          g2_ws, g2_wd, g2_as, g2_ad, watt1, watt2);

    // ---- CSR build (dst-sorted edge order) ----
    zero_deg_k<<<(Nn + 255) / 256, 256>>>(deg);
    hist_k<<<(Ee + 255) / 256, 256>>>(dst, deg);
    scan_k<<<1, SCAN_T>>>(deg, roff, cur);
    bucket_k<<<(Ee + 255) / 256, 256>>>(dst, cur, eord);

    // 1) input embeddings (weights read directly from inputs)
    gemm(x,        INWd, W_rna,  EMBd, h0,        HDd, b_rna,  Nn, EMBd, RNAd,  0);
    gemm(x + RNAd, INWd, W_prot, EMBd, h0 + EMBd, HDd, b_prot, Nn, EMBd, PROTd, 0);

    // 2) GAT layer 1
    gemm(h0, HDd, Bf1, 1024, fz, 1024, biasf1, Nn, 1024, HDd, 0);
    attn8_k<<<Nn, 256>>>(h0, watt1, asrc, adst);
    agg_fused_k<<<Nn, 128>>>(src, eord, roff, asrc, adst, fz, buf);

    // 3) GAT layer 2
    gemm(buf, HDd, Bf2, 1024, fz, 1024, biasf2, Nn, 1024, HDd, 0);
    attn8_k<<<Nn, 256>>>(buf, watt2, asrc, adst);
    agg_fused_k<<<Nn, 128>>>(src, eord, roff, asrc, adst, fz, h0);

    // 4) embedding = relu(h2 @ agg_w + agg_b) -> output
    gemm(h0, HDd, agg_w, HIDd, out_emb, HIDd, agg_b, Nn, HIDd, HDd, 1);

    // 5) packed decoders: xs[:, :256]=rna_d, xs[:, 256:]=prot_d
    gemm(out_emb, HIDd, Bdec, 512, xs, 512, bdec, Nn, 512, HIDd, 0);

    // 6) reconstructions (A = xs at lda=512, offsets 0 / 256)
    gemm(xs,       512, rr_w, RNAd,  out_rna,  RNAd,  rr_b, Nn, RNAd,  EMBd, 0);
    gemm(xs + 256, 512, rp_w, PROTd, out_prot, PROTd, rp_b, Nn, PROTd, EMBd, 0);
}

// round 11
// speedup vs baseline: 4.9459x; 1.0326x over previous
#include <cuda_runtime.h>
#include <cuda_fp16.h>
#include <math.h>
#include <stdint.h>

// Problem constants
#define Nn    20000
#define Ee    320000
#define RNAd  2000
#define PROTd 100
#define EMBd  256
#define HIDd  128
#define NH    4
#define HDd   512
#define INWd  2100

// ---------------- scratch (device globals: allocation-free) ----------------
__device__ float    g_h0  [(size_t)Nn * HDd];    // layer activations
__device__ float    g_buf [(size_t)Nn * HDd];    // layer activations
__device__ float    g_fz  [(size_t)Nn * 1024];   // fused GEMM out (residual half used)
__device__ __half   g_msg [(size_t)Nn * HDd];    // fp16 messages (fz cols 0-511)
__device__ float    g_asrc[Nn * NH];
__device__ float    g_adst[Nn * NH];
__device__ float    g_wr  [1700000];             // packed weight arena
__device__ int      g_deg [Nn];
__device__ int      g_cur [Nn];
__device__ int      g_roff[Nn + 1];
__device__ int      g_eord[Ee];

// ============================================================================
// prep_k: single launch doing all weight packing / bias concat (f32)
// mode 1: horizontal pack [s1|s2]; row width w1+w2
// mode 2: fused-layer bias: d[i] = (i<w1) ? 0 : s1[i-w1]+s2[i-w1]
// ============================================================================
struct Job { const float* s1; const float* s2; float* d; int n; int w1; int w2; int mode; };
struct Jobs { Job j[8]; int cnt; };

__global__ void prep_k(Jobs jobs)
{
    int t = blockIdx.y;
    if (t >= jobs.cnt) return;
    Job jb = jobs.j[t];
    int stride = gridDim.x * blockDim.x;
    for (int i = blockIdx.x * blockDim.x + threadIdx.x; i < jb.n; i += stride) {
        if (jb.mode == 1) {
            int w = jb.w1 + jb.w2;
            int k = i / w, c = i - k * w;
            jb.d[i] = (c < jb.w1) ? jb.s1[(size_t)k * jb.w1 + c]
                                  : jb.s2[(size_t)k * jb.w2 + (c - jb.w1)];
        } else {
            jb.d[i] = (i < jb.w1) ? 0.f : (jb.s1[i - jb.w1] + jb.s2[i - jb.w1]);
        }
    }
}

// ---------------- folded recon bias: out[i] = rb[i] + sum_k db[k]*W[k,N]+... -
__global__ void bcomb_k(const float* __restrict__ db, const float* __restrict__ W,
                        const float* __restrict__ rb, float* __restrict__ out,
                        int N, int K)
{
    int i = blockIdx.x * blockDim.x + threadIdx.x;
    if (i >= N) return;
    float s = rb[i];
    for (int k = 0; k < K; k++) s += db[k] * W[(size_t)k * N + i];
    out[i] = s;
}

// ---------------- Wattn (both layers): 16 blocks; c<8 layer1, c>=8 layer2 ---
__global__ void wattn2_k(const float* __restrict__ ws1, const float* __restrict__ wd1,
                         const float* __restrict__ as1, const float* __restrict__ ad1,
                         const float* __restrict__ ws2, const float* __restrict__ wd2,
                         const float* __restrict__ as2, const float* __restrict__ ad2,
                         float* __restrict__ w1, float* __restrict__ w2)
{
    int c = blockIdx.x;
    int layer = c >> 3;
    int cc = c & 7;
    int t = threadIdx.x;
    const float* ws = layer ? ws2 : ws1;
    const float* wd = layer ? wd2 : wd1;
    const float* a_s = layer ? as2 : as1;
    const float* a_d = layer ? ad2 : ad1;
    float* wo = layer ? w2 : w1;
    const float* w = (cc < 4) ? ws : wd;
    int hh = (cc < 4) ? cc : (cc - 4);
    const float* a = (cc < 4) ? (a_s + hh * HIDd) : (a_d + hh * HIDd);
    #pragma unroll
    for (int kq = 0; kq < 4; kq++) {
        int k = t + kq * 128;
        float s = 0.f;
        const float* wr = w + (size_t)k * HDd + hh * HIDd;
        for (int d = 0; d < HIDd; d++) s += wr[d] * a[d];
        wo[cc * HDd + k] = s;
    }
}

// ---------------- attn coefs from h directly: 8 warps = 8 outputs ----------
__global__ __launch_bounds__(256) void attn8_k(
    const float* __restrict__ h, const float* __restrict__ wattn,
    float* __restrict__ asrc, float* __restrict__ adst)
{
    int n    = blockIdx.x;
    int c    = threadIdx.x >> 5;
    int lane = threadIdx.x & 31;
    const float4* hp = reinterpret_cast<const float4*>(h + (size_t)n * HDd);
    const float4* wp = reinterpret_cast<const float4*>(wattn + c * HDd);
    float s = 0.f;
    #pragma unroll
    for (int q = 0; q < 4; q++) {
        float4 a = hp[lane + q * 32];
        float4 b = wp[lane + q * 32];
        s += a.x * b.x + a.y * b.y + a.z * b.z + a.w * b.w;
    }
    #pragma unroll
    for (int o = 16; o; o >>= 1) s += __shfl_xor_sync(0xffffffffu, s, o);
    if (lane == 0) {
        if (c < 4) asrc[n * NH + c]       = s;
        else       adst[n * NH + (c - 4)] = s;
    }
}

// ============================================================================
// FP16 mma.sync GEMM (f32 in gmem, fp16 at smem store; f32 accum).
// Block tile 128x128x16, 8 warps, warp tile 64x32, mma.m16n8k16.
// Optional msgout: blocks with bn<512 write __half2 messages instead of f32 C.
// ============================================================================
__device__ __forceinline__ void mma_f16(float* d, const uint32_t* a, const uint32_t* b) {
    asm volatile(
        "mma.sync.aligned.m16n8k16.row.col.f32.f16.f16.f32 "
        "{%0,%1,%2,%3}, {%4,%5,%6,%7}, {%8,%9}, {%0,%1,%2,%3};"
        : "+f"(d[0]), "+f"(d[1]), "+f"(d[2]), "+f"(d[3])
        : "r"(a[0]), "r"(a[1]), "r"(a[2]), "r"(a[3]), "r"(b[0]), "r"(b[1]));
}

__global__ __launch_bounds__(256, 2) void mma_gemm_k(
    const float* __restrict__ A, int lda,
    const float* __restrict__ B, int ldb,
    float* __restrict__ C, int ldc,
    const float* __restrict__ bias1,
    int M, int N, int K, int act, __half* __restrict__ msgout)
{
    __shared__ __align__(16) half2 Ash[2][1024];
    __shared__ __align__(16) half2 Bsh[2][1024];

    const int tid  = threadIdx.x;
    const int lane = tid & 31;
    const int warp = tid >> 5;
    const int wm   = warp >> 2;    // 0..1
    const int wn   = warp & 3;     // 0..3
    const int bm   = blockIdx.y * 128;
    const int bn   = blockIdx.x * 128;
    const bool ismsg = (msgout != nullptr) && (bn < 512);

    const int arow = tid >> 1;
    const int asg  = tid & 1;
    const bool rok = (bm + arow) < M;
    const float* Arow = A + (size_t)(bm + arow) * lda;
    const int a_mt = arow >> 4;
    const int a_q  = ((arow >> 3) & 1) + 2 * asg;
    const int a_sl = (a_mt * 4 + a_q) * 32 + (arow & 7) * 4;

    const int bnn = tid & 127;
    const int bq  = tid >> 7;
    const bool nok = (bn + bnn) < N;
    const int b_nt = bnn >> 3;
    const int b_sl = (bq * 16 + b_nt) * 32 + (bnn & 7) * 4;

    float a8[8], b8[8];
    float acc[4][4][4];
    #pragma unroll
    for (int i = 0; i < 4; i++)
        #pragma unroll
        for (int j = 0; j < 4; j++)
            #pragma unroll
            for (int r = 0; r < 4; r++) acc[i][j][r] = 0.f;

    const int KT = (K + 15) >> 4;

    {
        const int ka = asg * 8;
        if (rok && ka + 7 < K) {
            float4 v0 = *reinterpret_cast<const float4*>(Arow + ka);
            float4 v1 = *reinterpret_cast<const float4*>(Arow + ka + 4);
            a8[0]=v0.x; a8[1]=v0.y; a8[2]=v0.z; a8[3]=v0.w;
            a8[4]=v1.x; a8[5]=v1.y; a8[6]=v1.z; a8[7]=v1.w;
        } else {
            #pragma unroll
            for (int i = 0; i < 8; i++)
                a8[i] = (rok && ka + i < K) ? Arow[ka + i] : 0.f;
        }
        const int kb = bq * 8;
        #pragma unroll
        for (int i = 0; i < 8; i++)
            b8[i] = (nok && kb + i < K) ? __ldg(B + (size_t)(kb + i) * ldb + bn + bnn) : 0.f;
    }

    for (int t = 0; t < KT; t++) {
        const int buf = t & 1;

        {
            half2 ph[4];
            ph[0] = __floats2half2_rn(a8[0], a8[1]);
            ph[1] = __floats2half2_rn(a8[2], a8[3]);
            ph[2] = __floats2half2_rn(a8[4], a8[5]);
            ph[3] = __floats2half2_rn(a8[6], a8[7]);
            *reinterpret_cast<float4*>(&Ash[buf][a_sl]) = *reinterpret_cast<float4*>(ph);
            ph[0] = __floats2half2_rn(b8[0], b8[1]);
            ph[1] = __floats2half2_rn(b8[2], b8[3]);
            ph[2] = __floats2half2_rn(b8[4], b8[5]);
            ph[3] = __floats2half2_rn(b8[6], b8[7]);
            *reinterpret_cast<float4*>(&Bsh[buf][b_sl]) = *reinterpret_cast<float4*>(ph);
        }
        __syncthreads();

        if (t + 1 < KT) {
            const int ka = (t + 1) * 16 + asg * 8;
            if (rok && ka + 7 < K) {
                float4 v0 = *reinterpret_cast<const float4*>(Arow + ka);
                float4 v1 = *reinterpret_cast<const float4*>(Arow + ka + 4);
                a8[0]=v0.x; a8[1]=v0.y; a8[2]=v0.z; a8[3]=v0.w;
                a8[4]=v1.x; a8[5]=v1.y; a8[6]=v1.z; a8[7]=v1.w;
            } else {
                #pragma unroll
                for (int i = 0; i < 8; i++)
                    a8[i] = (rok && ka + i < K) ? Arow[ka + i] : 0.f;
            }
            const int kb = (t + 1) * 16 + bq * 8;
            if (kb + 7 < K) {
                #pragma unroll
                for (int i = 0; i < 8; i++)
                    b8[i] = nok ? __ldg(B + (size_t)(kb + i) * ldb + bn + bnn) : 0.f;
            } else {
                #pragma unroll
                for (int i = 0; i < 8; i++)
                    b8[i] = (nok && kb + i < K) ? __ldg(B + (size_t)(kb + i) * ldb + bn + bnn) : 0.f;
            }
        }

        const uint32_t* As32 = reinterpret_cast<const uint32_t*>(&Ash[buf][0]);
        const uint32_t* Bs32 = reinterpret_cast<const uint32_t*>(&Bsh[buf][0]);
        uint32_t af[4][4], bf[4][2];
        #pragma unroll
        for (int i = 0; i < 4; i++) {
            int mt = wm * 4 + i;
            #pragma unroll
            for (int q = 0; q < 4; q++)
                af[i][q] = As32[(mt * 4 + q) * 32 + lane];
        }
        #pragma unroll
        for (int j = 0; j < 4; j++) {
            int nt = wn * 4 + j;
            bf[j][0] = Bs32[nt * 32 + lane];
            bf[j][1] = Bs32[(16 + nt) * 32 + lane];
        }
        #pragma unroll
        for (int i = 0; i < 4; i++)
            #pragma unroll
            for (int j = 0; j < 4; j++)
                mma_f16(acc[i][j], af[i], bf[j]);
        __syncthreads();
    }

    // ---- epilogue ----
    #pragma unroll
    for (int i = 0; i < 4; i++) {
        int row0 = bm + wm * 64 + i * 16 + (lane >> 2);
        #pragma unroll
        for (int j = 0; j < 4; j++) {
            int col0 = bn + wn * 32 + j * 8 + ((lane & 3) << 1);
            float bv0 = 0.f, bv1 = 0.f;
            if (bias1) {
                if (col0 < N)     bv0 = bias1[col0];
                if (col0 + 1 < N) bv1 = bias1[col0 + 1];
            }
            #pragma unroll
            for (int h = 0; h < 2; h++) {
                int row = row0 + 8 * h;
                if (row >= M) continue;
                float v0 = acc[i][j][2 * h + 0] + bv0;
                float v1 = acc[i][j][2 * h + 1] + bv1;
                if (act) { v0 = fmaxf(v0, 0.f); v1 = fmaxf(v1, 0.f); }
                if (ismsg) {
                    reinterpret_cast<__half2*>(msgout)[((size_t)row * 512 + col0) >> 1] =
                        __floats2half2_rn(v0, v1);
                } else {
                    float* cp = C + (size_t)row * ldc + col0;
                    if (col0 + 1 < N)  *(float2*)cp = make_float2(v0, v1);
                    else if (col0 < N) *cp = v0;
                }
            }
        }
    }
}

// ---------------- CSR build (once per launch) ----------------
__global__ void zero_deg_k(int* __restrict__ deg)
{
    int i = blockIdx.x * blockDim.x + threadIdx.x;
    if (i < Nn) deg[i] = 0;
}

__global__ void hist_k(const int* __restrict__ dst, int* __restrict__ deg)
{
    int e = blockIdx.x * blockDim.x + threadIdx.x;
    if (e < Ee) atomicAdd(&deg[dst[e]], 1);
}

#define SCAN_T 1024
#define SCAN_C 20
__global__ __launch_bounds__(SCAN_T) void scan_k(const int* __restrict__ deg,
                                                 int* __restrict__ roff,
                                                 int* __restrict__ cur)
{
    __shared__ int ss[SCAN_T];
    int t = threadIdx.x;
    int base = t * SCAN_C;
    int loc[SCAN_C];
    int sum = 0;
    #pragma unroll
    for (int i = 0; i < SCAN_C; i++) {
        int idx = base + i;
        int v = (idx < Nn) ? deg[idx] : 0;
        loc[i] = sum;
        sum += v;
    }
    ss[t] = sum;
    __syncthreads();
    int own = sum;
    for (int off = 1; off < SCAN_T; off <<= 1) {
        int v = (t >= off) ? ss[t - off] : 0;
        __syncthreads();
        ss[t] += v;
        __syncthreads();
    }
    int excl = ss[t] - own;
    #pragma unroll
    for (int i = 0; i < SCAN_C; i++) {
        int idx = base + i;
        if (idx < Nn) { roff[idx] = excl + loc[i]; cur[idx] = excl + loc[i]; }
    }
    if (t == SCAN_T - 1) roff[Nn] = ss[SCAN_T - 1];
}

__global__ void bucket_k(const int* __restrict__ dst, int* __restrict__ cur,
                         int* __restrict__ eord)
{
    int e = blockIdx.x * blockDim.x + threadIdx.x;
    if (e < Ee) {
        int pos = atomicAdd(&cur[dst[e]], 1);
        eord[pos] = e;
    }
}

// ============================================================================
// Fused segment softmax + gather-aggregate + residual + ReLU.
// Block = dst node, 4 warps = 4 heads; lane covers 4 feats.
// Messages read as fp16 (half the bytes); accumulation in f32.
// ============================================================================
__global__ __launch_bounds__(128) void agg_fused_k(
    const int* __restrict__ src, const int* __restrict__ eord,
    const int* __restrict__ roff,
    const float* __restrict__ asrc, const float* __restrict__ adst,
    const __half* __restrict__ msg, const float* __restrict__ fz,
    float* __restrict__ out)
{
    int n    = blockIdx.x;
    int h    = threadIdx.x >> 5;
    int lane = threadIdx.x & 31;
    int r0 = roff[n], r1 = roff[n + 1];
    float adn = adst[n * NH + h];

    // pass 1: segment max (lanes stride edges)
    float m = -3.4e38f;
    for (int j = r0 + lane; j < r1; j += 32) {
        int eid = __ldg(eord + j);
        float v = __ldg(asrc + __ldg(src + eid) * NH + h) + adn;
        v = v > 0.f ? v : 0.2f * v;
        m = fmaxf(m, v);
    }
    #pragma unroll
    for (int o = 16; o; o >>= 1) m = fmaxf(m, __shfl_xor_sync(0xffffffffu, m, o));

    // pass 2: exp + weighted fp16 gather in one sweep
    float s = 0.f;
    float4 acc = make_float4(0.f, 0.f, 0.f, 0.f);
    for (int j = r0; j < r1; j++) {
        int eid = __ldg(eord + j);
        int sn  = __ldg(src + eid);
        float v = __ldg(asrc + sn * NH + h) + adn;
        v = v > 0.f ? v : 0.2f * v;
        float ex = __expf(v - m);
        s += ex;
        uint2 u = *reinterpret_cast<const uint2*>(msg + (size_t)sn * HDd + h * HIDd + lane * 4);
        float2 va = __half22float2(*reinterpret_cast<const __half2*>(&u.x));
        float2 vb = __half22float2(*reinterpret_cast<const __half2*>(&u.y));
        acc.x += ex * va.x; acc.y += ex * va.y;
        acc.z += ex * vb.x; acc.w += ex * vb.y;
    }
    float iv = (r1 > r0) ? 1.f / (s + 1e-16f) : 0.f;

    float4 r = *reinterpret_cast<const float4*>(fz + (size_t)n * 1024 + 512 + h * HIDd + lane * 4);
    float4 o;
    o.x = fmaxf(r.x + acc.x * iv, 0.f);
    o.y = fmaxf(r.y + acc.y * iv, 0.f);
    o.z = fmaxf(r.z + acc.z * iv, 0.f);
    o.w = fmaxf(r.w + acc.w * iv, 0.f);
    *reinterpret_cast<float4*>(out + (size_t)n * HDd + h * HIDd + lane * 4) = o;
}

// ---------------- host helpers ----------------
static inline void gemm(const float* A, int lda, const float* B, int ldb,
                        float* C, int ldc, const float* b1,
                        int M, int N, int K, int act, __half* msgout = nullptr)
{
    dim3 grid((N + 127) / 128, (M + 127) / 128);
    mma_gemm_k<<<grid, 256>>>(A, lda, B, ldb, C, ldc, b1, M, N, K, act, msgout);
}

extern "C" void kernel_launch(void* const* d_in, const int* in_sizes, int n_in,
                              void* d_out, int out_size)
{
    const float* x      = (const float*)d_in[0];
    const int*   ei     = (const int*)  d_in[1];
    const float* W_rna  = (const float*)d_in[2];
    const float* b_rna  = (const float*)d_in[3];
    const float* W_prot = (const float*)d_in[4];
    const float* b_prot = (const float*)d_in[5];
    const float* g1_ws  = (const float*)d_in[6];
    const float* g1_wd  = (const float*)d_in[7];
    const float* g1_as  = (const float*)d_in[8];
    const float* g1_ad  = (const float*)d_in[9];
    const float* g1_b   = (const float*)d_in[10];
    const float* l1_w   = (const float*)d_in[11];
    const float* l1_b   = (const float*)d_in[12];
    const float* g2_ws  = (const float*)d_in[13];
    const float* g2_wd  = (const float*)d_in[14];
    const float* g2_as  = (const float*)d_in[15];
    const float* g2_ad  = (const float*)d_in[16];
    const float* g2_b   = (const float*)d_in[17];
    const float* l2_w   = (const float*)d_in[18];
    const float* l2_b   = (const float*)d_in[19];
    const float* agg_w  = (const float*)d_in[20];
    const float* agg_b  = (const float*)d_in[21];
    const float* dr_w   = (const float*)d_in[22];
    const float* dr_b   = (const float*)d_in[23];
    const float* dp_w   = (const float*)d_in[24];
    const float* dp_b   = (const float*)d_in[25];
    const float* rr_w   = (const float*)d_in[26];
    const float* rr_b   = (const float*)d_in[27];
    const float* rp_w   = (const float*)d_in[28];
    const float* rp_b   = (const float*)d_in[29];

    const int* src = ei;
    const int* dst = ei + Ee;

    float* out = (float*)d_out;
    float* out_rna  = out;                                     // [Nn, 2000]
    float* out_prot = out + (size_t)Nn * RNAd;                 // [Nn, 100]
    float* out_emb  = out + (size_t)Nn * (RNAd + PROTd);       // [Nn, 128]

    float *h0, *buf, *fz, *asrc, *adst, *wr;
    __half* msg;
    int *deg, *cur, *roff, *eord;
    cudaGetSymbolAddress((void**)&h0,   g_h0);
    cudaGetSymbolAddress((void**)&buf,  g_buf);
    cudaGetSymbolAddress((void**)&fz,   g_fz);
    cudaGetSymbolAddress((void**)&msg,  g_msg);
    cudaGetSymbolAddress((void**)&asrc, g_asrc);
    cudaGetSymbolAddress((void**)&adst, g_adst);
    cudaGetSymbolAddress((void**)&wr,   g_wr);
    cudaGetSymbolAddress((void**)&deg,  g_deg);
    cudaGetSymbolAddress((void**)&cur,  g_cur);
    cudaGetSymbolAddress((void**)&roff, g_roff);
    cudaGetSymbolAddress((void**)&eord, g_eord);

    // ---- packed weight arena (f32; fp16 conversion happens in GEMM loader) ----
    size_t wo = 0;
    auto arena = [&](size_t n) -> float* { float* p = wr + wo; wo += n; return p; };
    float* Bf1     = arena((size_t)512 * 1024);
    float* Bf2     = arena((size_t)512 * 1024);
    float* biasf1  = arena(1024);
    float* biasf2  = arena(1024);
    float* watt1   = arena(8 * 512);
    float* watt2   = arena(8 * 512);
    float* Wc_rna  = arena((size_t)HIDd * RNAd);   // dr_w @ rr_w  [128,2000]
    float* Wc_prot = arena((size_t)HIDd * PROTd);  // dp_w @ rp_w  [128,100]
    float* bc_rna  = arena(RNAd);
    float* bc_prot = arena(PROTd);

    Jobs jobs;
    int jc = 0;
    auto addj = [&](const float* s1, const float* s2, float* d, int n, int w1, int w2, int mode) {
        jobs.j[jc++] = Job{s1, s2, d, n, w1, w2, mode};
    };
    addj(g1_ws, l1_w, Bf1, 512 * 1024, 512, 512, 1);
    addj(g2_ws, l2_w, Bf2, 512 * 1024, 512, 512, 1);
    addj(g1_b,  l1_b, biasf1, 1024, 512, 0, 2);
    addj(g2_b,  l2_b, biasf2, 1024, 512, 0, 2);
    jobs.cnt = jc;
    prep_k<<<dim3(64, jc), 256>>>(jobs);

    wattn2_k<<<16, 128>>>(g1_ws, g1_wd, g1_as, g1_ad,
                          g2_ws, g2_wd, g2_as, g2_ad, watt1, watt2);

    // ---- folded decoder->recon weights & biases ----
    gemm(dr_w, EMBd, rr_w, RNAd,  Wc_rna,  RNAd,  nullptr, HIDd, RNAd,  EMBd, 0);
    gemm(dp_w, EMBd, rp_w, PROTd, Wc_prot, PROTd, nullptr, HIDd, PROTd, EMBd, 0);
    bcomb_k<<<(RNAd + 127) / 128, 128>>>(dr_b, rr_w, rr_b, bc_rna, RNAd, EMBd);
    bcomb_k<<<(PROTd + 127) / 128, 128>>>(dp_b, rp_w, rp_b, bc_prot, PROTd, EMBd);

    // ---- CSR build (dst-sorted edge order) ----
    zero_deg_k<<<(Nn + 255) / 256, 256>>>(deg);
    hist_k<<<(Ee + 255) / 256, 256>>>(dst, deg);
    scan_k<<<1, SCAN_T>>>(deg, roff, cur);
    bucket_k<<<(Ee + 255) / 256, 256>>>(dst, cur, eord);

    // 1) input embeddings
    gemm(x,        INWd, W_rna,  EMBd, h0,        HDd, b_rna,  Nn, EMBd, RNAd,  0);
    gemm(x + RNAd, INWd, W_prot, EMBd, h0 + EMBd, HDd, b_prot, Nn, EMBd, PROTd, 0);

    // 2) GAT layer 1 (messages -> fp16 msg buffer, residual -> fz cols 512+)
    gemm(h0, HDd, Bf1, 1024, fz, 1024, biasf1, Nn, 1024, HDd, 0, msg);
    attn8_k<<<Nn, 256>>>(h0, watt1, asrc, adst);
    agg_fused_k<<<Nn, 128>>>(src, eord, roff, asrc, adst, msg, fz, buf);

    // 3) GAT layer 2
    gemm(buf, HDd, Bf2, 1024, fz, 1024, biasf2, Nn, 1024, HDd, 0, msg);
    attn8_k<<<Nn, 256>>>(buf, watt2, asrc, adst);
    agg_fused_k<<<Nn, 128>>>(src, eord, roff, asrc, adst, msg, fz, h0);

    // 4) embedding = relu(h2 @ agg_w + agg_b) -> output
    gemm(h0, HDd, agg_w, HIDd, out_emb, HIDd, agg_b, Nn, HIDd, HDd, 1);

    // 5+6) collapsed decoder+reconstruction (K=128)
    gemm(out_emb, HIDd, Wc_rna,  RNAd,  out_rna,  RNAd,  bc_rna,  Nn, RNAd,  HIDd, 0);
    gemm(out_emb, HIDd, Wc_prot, PROTd, out_prot, PROTd, bc_prot, Nn, PROTd, HIDd, 0);
}

// round 13
// speedup vs baseline: 5.5264x; 1.1174x over previous
#include <cuda_runtime.h>
#include <cuda_fp16.h>
#include <math.h>
#include <stdint.h>

// Problem constants
#define Nn    20000
#define Ee    320000
#define RNAd  2000
#define PROTd 100
#define EMBd  256
#define HIDd  128
#define NH    4
#define HDd   512
#define INWd  2100

// ---------------- scratch (device globals: allocation-free) ----------------
__device__ float    g_h0  [(size_t)Nn * HDd];    // layer activations
__device__ float    g_buf [(size_t)Nn * HDd];    // layer activations
__device__ float    g_fz  [(size_t)Nn * 1024];   // fused GEMM out (residual half used)
__device__ __half   g_msg [(size_t)Nn * HDd];    // fp16 messages (fz cols 0-511)
__device__ float    g_asrc[Nn * NH];
__device__ float    g_adst[Nn * NH];
__device__ float    g_wr  [1700000];             // packed weight arena
__device__ int      g_deg [Nn];
__device__ int      g_cur [Nn];
__device__ int      g_roff[Nn + 1];
__device__ int      g_eord[Ee];

// ============================================================================
// prep_k: single launch doing all weight packing / bias concat (f32)
// ============================================================================
struct Job { const float* s1; const float* s2; float* d; int n; int w1; int w2; int mode; };
struct Jobs { Job j[8]; int cnt; };

__global__ void prep_k(Jobs jobs)
{
    int t = blockIdx.y;
    if (t >= jobs.cnt) return;
    Job jb = jobs.j[t];
    int stride = gridDim.x * blockDim.x;
    for (int i = blockIdx.x * blockDim.x + threadIdx.x; i < jb.n; i += stride) {
        if (jb.mode == 1) {
            int w = jb.w1 + jb.w2;
            int k = i / w, c = i - k * w;
            jb.d[i] = (c < jb.w1) ? jb.s1[(size_t)k * jb.w1 + c]
                                  : jb.s2[(size_t)k * jb.w2 + (c - jb.w1)];
        } else {
            jb.d[i] = (i < jb.w1) ? 0.f : (jb.s1[i - jb.w1] + jb.s2[i - jb.w1]);
        }
    }
}

// ---------------- folded recon bias: out[i] = rb[i] + sum_k db[k]*W[k,i] ----
__global__ void bcomb_k(const float* __restrict__ db, const float* __restrict__ W,
                        const float* __restrict__ rb, float* __restrict__ out,
                        int N, int K)
{
    int i = blockIdx.x * blockDim.x + threadIdx.x;
    if (i >= N) return;
    float s = rb[i];
    for (int k = 0; k < K; k++) s += db[k] * W[(size_t)k * N + i];
    out[i] = s;
}

// ---------------- Wattn (both layers): 16 blocks; c<8 layer1, c>=8 layer2 ---
__global__ void wattn2_k(const float* __restrict__ ws1, const float* __restrict__ wd1,
                         const float* __restrict__ as1, const float* __restrict__ ad1,
                         const float* __restrict__ ws2, const float* __restrict__ wd2,
                         const float* __restrict__ as2, const float* __restrict__ ad2,
                         float* __restrict__ w1, float* __restrict__ w2)
{
    int c = blockIdx.x;
    int layer = c >> 3;
    int cc = c & 7;
    int t = threadIdx.x;
    const float* ws = layer ? ws2 : ws1;
    const float* wd = layer ? wd2 : wd1;
    const float* a_s = layer ? as2 : as1;
    const float* a_d = layer ? ad2 : ad1;
    float* wo = layer ? w2 : w1;
    const float* w = (cc < 4) ? ws : wd;
    int hh = (cc < 4) ? cc : (cc - 4);
    const float* a = (cc < 4) ? (a_s + hh * HIDd) : (a_d + hh * HIDd);
    #pragma unroll
    for (int kq = 0; kq < 4; kq++) {
        int k = t + kq * 128;
        float s = 0.f;
        const float* wr = w + (size_t)k * HDd + hh * HIDd;
        for (int d = 0; d < HIDd; d++) s += wr[d] * a[d];
        wo[cc * HDd + k] = s;
    }
}

// ---------------- attn coefs from h directly: 8 warps = 8 outputs ----------
__global__ __launch_bounds__(256) void attn8_k(
    const float* __restrict__ h, const float* __restrict__ wattn,
    float* __restrict__ asrc, float* __restrict__ adst)
{
    int n    = blockIdx.x;
    int c    = threadIdx.x >> 5;
    int lane = threadIdx.x & 31;
    const float4* hp = reinterpret_cast<const float4*>(h + (size_t)n * HDd);
    const float4* wp = reinterpret_cast<const float4*>(wattn + c * HDd);
    float s = 0.f;
    #pragma unroll
    for (int q = 0; q < 4; q++) {
        float4 a = hp[lane + q * 32];
        float4 b = wp[lane + q * 32];
        s += a.x * b.x + a.y * b.y + a.z * b.z + a.w * b.w;
    }
    #pragma unroll
    for (int o = 16; o; o >>= 1) s += __shfl_xor_sync(0xffffffffu, s, o);
    if (lane == 0) {
        if (c < 4) asrc[n * NH + c]       = s;
        else       adst[n * NH + (c - 4)] = s;
    }
}

// ============================================================================
// FP16 mma.sync GEMM (f32 in gmem, fp16 at smem store; f32 accum).
// ============================================================================
__device__ __forceinline__ void mma_f16(float* d, const uint32_t* a, const uint32_t* b) {
    asm volatile(
        "mma.sync.aligned.m16n8k16.row.col.f32.f16.f16.f32 "
        "{%0,%1,%2,%3}, {%4,%5,%6,%7}, {%8,%9}, {%0,%1,%2,%3};"
        : "+f"(d[0]), "+f"(d[1]), "+f"(d[2]), "+f"(d[3])
        : "r"(a[0]), "r"(a[1]), "r"(a[2]), "r"(a[3]), "r"(b[0]), "r"(b[1]));
}

__global__ __launch_bounds__(256, 2) void mma_gemm_k(
    const float* __restrict__ A, int lda,
    const float* __restrict__ B, int ldb,
    float* __restrict__ C, int ldc,
    const float* __restrict__ bias1,
    int M, int N, int K, int act, __half* __restrict__ msgout)
{
    __shared__ __align__(16) half2 Ash[2][1024];
    __shared__ __align__(16) half2 Bsh[2][1024];

    const int tid  = threadIdx.x;
    const int lane = tid & 31;
    const int warp = tid >> 5;
    const int wm   = warp >> 2;
    const int wn   = warp & 3;
    const int bm   = blockIdx.y * 128;
    const int bn   = blockIdx.x * 128;
    const bool ismsg = (msgout != nullptr) && (bn < 512);

    const int arow = tid >> 1;
    const int asg  = tid & 1;
    const bool rok = (bm + arow) < M;
    const float* Arow = A + (size_t)(bm + arow) * lda;
    const int a_mt = arow >> 4;
    const int a_q  = ((arow >> 3) & 1) + 2 * asg;
    const int a_sl = (a_mt * 4 + a_q) * 32 + (arow & 7) * 4;

    const int bnn = tid & 127;
    const int bq  = tid >> 7;
    const bool nok = (bn + bnn) < N;
    const int b_nt = bnn >> 3;
    const int b_sl = (bq * 16 + b_nt) * 32 + (bnn & 7) * 4;

    float a8[8], b8[8];
    float acc[4][4][4];
    #pragma unroll
    for (int i = 0; i < 4; i++)
        #pragma unroll
        for (int j = 0; j < 4; j++)
            #pragma unroll
            for (int r = 0; r < 4; r++) acc[i][j][r] = 0.f;

    const int KT = (K + 15) >> 4;

    {
        const int ka = asg * 8;
        if (rok && ka + 7 < K) {
            float4 v0 = *reinterpret_cast<const float4*>(Arow + ka);
            float4 v1 = *reinterpret_cast<const float4*>(Arow + ka + 4);
            a8[0]=v0.x; a8[1]=v0.y; a8[2]=v0.z; a8[3]=v0.w;
            a8[4]=v1.x; a8[5]=v1.y; a8[6]=v1.z; a8[7]=v1.w;
        } else {
            #pragma unroll
            for (int i = 0; i < 8; i++)
                a8[i] = (rok && ka + i < K) ? Arow[ka + i] : 0.f;
        }
        const int kb = bq * 8;
        #pragma unroll
        for (int i = 0; i < 8; i++)
            b8[i] = (nok && kb + i < K) ? __ldg(B + (size_t)(kb + i) * ldb + bn + bnn) : 0.f;
    }

    for (int t = 0; t < KT; t++) {
        const int buf = t & 1;

        {
            half2 ph[4];
            ph[0] = __floats2half2_rn(a8[0], a8[1]);
            ph[1] = __floats2half2_rn(a8[2], a8[3]);
            ph[2] = __floats2half2_rn(a8[4], a8[5]);
            ph[3] = __floats2half2_rn(a8[6], a8[7]);
            *reinterpret_cast<float4*>(&Ash[buf][a_sl]) = *reinterpret_cast<float4*>(ph);
            ph[0] = __floats2half2_rn(b8[0], b8[1]);
            ph[1] = __floats2half2_rn(b8[2], b8[3]);
            ph[2] = __floats2half2_rn(b8[4], b8[5]);
            ph[3] = __floats2half2_rn(b8[6], b8[7]);
            *reinterpret_cast<float4*>(&Bsh[buf][b_sl]) = *reinterpret_cast<float4*>(ph);
        }
        __syncthreads();

        if (t + 1 < KT) {
            const int ka = (t + 1) * 16 + asg * 8;
            if (rok && ka + 7 < K) {
                float4 v0 = *reinterpret_cast<const float4*>(Arow + ka);
                float4 v1 = *reinterpret_cast<const float4*>(Arow + ka + 4);
                a8[0]=v0.x; a8[1]=v0.y; a8[2]=v0.z; a8[3]=v0.w;
                a8[4]=v1.x; a8[5]=v1.y; a8[6]=v1.z; a8[7]=v1.w;
            } else {
                #pragma unroll
                for (int i = 0; i < 8; i++)
                    a8[i] = (rok && ka + i < K) ? Arow[ka + i] : 0.f;
            }
            const int kb = (t + 1) * 16 + bq * 8;
            if (kb + 7 < K) {
                #pragma unroll
                for (int i = 0; i < 8; i++)
                    b8[i] = nok ? __ldg(B + (size_t)(kb + i) * ldb + bn + bnn) : 0.f;
            } else {
                #pragma unroll
                for (int i = 0; i < 8; i++)
                    b8[i] = (nok && kb + i < K) ? __ldg(B + (size_t)(kb + i) * ldb + bn + bnn) : 0.f;
            }
        }

        const uint32_t* As32 = reinterpret_cast<const uint32_t*>(&Ash[buf][0]);
        const uint32_t* Bs32 = reinterpret_cast<const uint32_t*>(&Bsh[buf][0]);
        uint32_t af[4][4], bf[4][2];
        #pragma unroll
        for (int i = 0; i < 4; i++) {
            int mt = wm * 4 + i;
            #pragma unroll
            for (int q = 0; q < 4; q++)
                af[i][q] = As32[(mt * 4 + q) * 32 + lane];
        }
        #pragma unroll
        for (int j = 0; j < 4; j++) {
            int nt = wn * 4 + j;
            bf[j][0] = Bs32[nt * 32 + lane];
            bf[j][1] = Bs32[(16 + nt) * 32 + lane];
        }
        #pragma unroll
        for (int i = 0; i < 4; i++)
            #pragma unroll
            for (int j = 0; j < 4; j++)
                mma_f16(acc[i][j], af[i], bf[j]);
        __syncthreads();
    }

    #pragma unroll
    for (int i = 0; i < 4; i++) {
        int row0 = bm + wm * 64 + i * 16 + (lane >> 2);
        #pragma unroll
        for (int j = 0; j < 4; j++) {
            int col0 = bn + wn * 32 + j * 8 + ((lane & 3) << 1);
            float bv0 = 0.f, bv1 = 0.f;
            if (bias1) {
                if (col0 < N)     bv0 = bias1[col0];
                if (col0 + 1 < N) bv1 = bias1[col0 + 1];
            }
            #pragma unroll
            for (int h = 0; h < 2; h++) {
                int row = row0 + 8 * h;
                if (row >= M) continue;
                float v0 = acc[i][j][2 * h + 0] + bv0;
                float v1 = acc[i][j][2 * h + 1] + bv1;
                if (act) { v0 = fmaxf(v0, 0.f); v1 = fmaxf(v1, 0.f); }
                if (ismsg) {
                    reinterpret_cast<__half2*>(msgout)[((size_t)row * 512 + col0) >> 1] =
                        __floats2half2_rn(v0, v1);
                } else {
                    float* cp = C + (size_t)row * ldc + col0;
                    if (col0 + 1 < N)  *(float2*)cp = make_float2(v0, v1);
                    else if (col0 < N) *cp = v0;
                }
            }
        }
    }
}

// ---------------- CSR build ----------------
__global__ void zero_deg_k(int* __restrict__ deg)
{
    int i = blockIdx.x * blockDim.x + threadIdx.x;
    if (i < Nn) deg[i] = 0;
}

__global__ void hist_k(const int* __restrict__ dst, int* __restrict__ deg)
{
    int e = blockIdx.x * blockDim.x + threadIdx.x;
    if (e < Ee) atomicAdd(&deg[dst[e]], 1);
}

#define SCAN_T 1024
#define SCAN_C 20
__global__ __launch_bounds__(SCAN_T) void scan_k(const int* __restrict__ deg,
                                                 int* __restrict__ roff,
                                                 int* __restrict__ cur)
{
    __shared__ int ss[SCAN_T];
    int t = threadIdx.x;
    int base = t * SCAN_C;
    int loc[SCAN_C];
    int sum = 0;
    #pragma unroll
    for (int i = 0; i < SCAN_C; i++) {
        int idx = base + i;
        int v = (idx < Nn) ? deg[idx] : 0;
        loc[i] = sum;
        sum += v;
    }
    ss[t] = sum;
    __syncthreads();
    int own = sum;
    for (int off = 1; off < SCAN_T; off <<= 1) {
        int v = (t >= off) ? ss[t - off] : 0;
        __syncthreads();
        ss[t] += v;
        __syncthreads();
    }
    int excl = ss[t] - own;
    #pragma unroll
    for (int i = 0; i < SCAN_C; i++) {
        int idx = base + i;
        if (idx < Nn) { roff[idx] = excl + loc[i]; cur[idx] = excl + loc[i]; }
    }
    if (t == SCAN_T - 1) roff[Nn] = ss[SCAN_T - 1];
}

__global__ void bucket_k(const int* __restrict__ dst, int* __restrict__ cur,
                         int* __restrict__ eord)
{
    int e = blockIdx.x * blockDim.x + threadIdx.x;
    if (e < Ee) {
        int pos = atomicAdd(&cur[dst[e]], 1);
        eord[pos] = e;
    }
}

// ============================================================================
// Fused segment softmax + gather-aggregate + residual + ReLU.
// ============================================================================
__global__ __launch_bounds__(128) void agg_fused_k(
    const int* __restrict__ src, const int* __restrict__ eord,
    const int* __restrict__ roff,
    const float* __restrict__ asrc, const float* __restrict__ adst,
    const __half* __restrict__ msg, const float* __restrict__ fz,
    float* __restrict__ out)
{
    int n    = blockIdx.x;
    int h    = threadIdx.x >> 5;
    int lane = threadIdx.x & 31;
    int r0 = roff[n], r1 = roff[n + 1];
    float adn = adst[n * NH + h];

    float m = -3.4e38f;
    for (int j = r0 + lane; j < r1; j += 32) {
        int eid = __ldg(eord + j);
        float v = __ldg(asrc + __ldg(src + eid) * NH + h) + adn;
        v = v > 0.f ? v : 0.2f * v;
        m = fmaxf(m, v);
    }
    #pragma unroll
    for (int o = 16; o; o >>= 1) m = fmaxf(m, __shfl_xor_sync(0xffffffffu, m, o));

    float s = 0.f;
    float4 acc = make_float4(0.f, 0.f, 0.f, 0.f);
    for (int j = r0; j < r1; j++) {
        int eid = __ldg(eord + j);
        int sn  = __ldg(src + eid);
        float v = __ldg(asrc + sn * NH + h) + adn;
        v = v > 0.f ? v : 0.2f * v;
        float ex = __expf(v - m);
        s += ex;
        uint2 u = *reinterpret_cast<const uint2*>(msg + (size_t)sn * HDd + h * HIDd + lane * 4);
        float2 va = __half22float2(*reinterpret_cast<const __half2*>(&u.x));
        float2 vb = __half22float2(*reinterpret_cast<const __half2*>(&u.y));
        acc.x += ex * va.x; acc.y += ex * va.y;
        acc.z += ex * vb.x; acc.w += ex * vb.y;
    }
    float iv = (r1 > r0) ? 1.f / (s + 1e-16f) : 0.f;

    float4 r = *reinterpret_cast<const float4*>(fz + (size_t)n * 1024 + 512 + h * HIDd + lane * 4);
    float4 o;
    o.x = fmaxf(r.x + acc.x * iv, 0.f);
    o.y = fmaxf(r.y + acc.y * iv, 0.f);
    o.z = fmaxf(r.z + acc.z * iv, 0.f);
    o.w = fmaxf(r.w + acc.w * iv, 0.f);
    *reinterpret_cast<float4*>(out + (size_t)n * HDd + h * HIDd + lane * 4) = o;
}

// ---------------- host helpers ----------------
static inline void gemm(const float* A, int lda, const float* B, int ldb,
                        float* C, int ldc, const float* b1,
                        int M, int N, int K, int act,
                        __half* msgout = nullptr, cudaStream_t st = 0)
{
    dim3 grid((N + 127) / 128, (M + 127) / 128);
    mma_gemm_k<<<grid, 256, 0, st>>>(A, lda, B, ldb, C, ldc, b1, M, N, K, act, msgout);
}

extern "C" void kernel_launch(void* const* d_in, const int* in_sizes, int n_in,
                              void* d_out, int out_size)
{
    const float* x      = (const float*)d_in[0];
    const int*   ei     = (const int*)  d_in[1];
    const float* W_rna  = (const float*)d_in[2];
    const float* b_rna  = (const float*)d_in[3];
    const float* W_prot = (const float*)d_in[4];
    const float* b_prot = (const float*)d_in[5];
    const float* g1_ws  = (const float*)d_in[6];
    const float* g1_wd  = (const float*)d_in[7];
    const float* g1_as  = (const float*)d_in[8];
    const float* g1_ad  = (const float*)d_in[9];
    const float* g1_b   = (const float*)d_in[10];
    const float* l1_w   = (const float*)d_in[11];
    const float* l1_b   = (const float*)d_in[12];
    const float* g2_ws  = (const float*)d_in[13];
    const float* g2_wd  = (const float*)d_in[14];
    const float* g2_as  = (const float*)d_in[15];
    const float* g2_ad  = (const float*)d_in[16];
    const float* g2_b   = (const float*)d_in[17];
    const float* l2_w   = (const float*)d_in[18];
    const float* l2_b   = (const float*)d_in[19];
    const float* agg_w  = (const float*)d_in[20];
    const float* agg_b  = (const float*)d_in[21];
    const float* dr_w   = (const float*)d_in[22];
    const float* dr_b   = (const float*)d_in[23];
    const float* dp_w   = (const float*)d_in[24];
    const float* dp_b   = (const float*)d_in[25];
    const float* rr_w   = (const float*)d_in[26];
    const float* rr_b   = (const float*)d_in[27];
    const float* rp_w   = (const float*)d_in[28];
    const float* rp_b   = (const float*)d_in[29];

    const int* src = ei;
    const int* dst = ei + Ee;

    float* out = (float*)d_out;
    float* out_rna  = out;                                     // [Nn, 2000]
    float* out_prot = out + (size_t)Nn * RNAd;                 // [Nn, 100]
    float* out_emb  = out + (size_t)Nn * (RNAd + PROTd);       // [Nn, 128]

    float *h0, *buf, *fz, *asrc, *adst, *wr;
    __half* msg;
    int *deg, *cur, *roff, *eord;
    cudaGetSymbolAddress((void**)&h0,   g_h0);
    cudaGetSymbolAddress((void**)&buf,  g_buf);
    cudaGetSymbolAddress((void**)&fz,   g_fz);
    cudaGetSymbolAddress((void**)&msg,  g_msg);
    cudaGetSymbolAddress((void**)&asrc, g_asrc);
    cudaGetSymbolAddress((void**)&adst, g_adst);
    cudaGetSymbolAddress((void**)&wr,   g_wr);
    cudaGetSymbolAddress((void**)&deg,  g_deg);
    cudaGetSymbolAddress((void**)&cur,  g_cur);
    cudaGetSymbolAddress((void**)&roff, g_roff);
    cudaGetSymbolAddress((void**)&eord, g_eord);

    // ---- packed weight arena ----
    size_t wo = 0;
    auto arena = [&](size_t n) -> float* { float* p = wr + wo; wo += n; return p; };
    float* Bf1     = arena((size_t)512 * 1024);
    float* Bf2     = arena((size_t)512 * 1024);
    float* biasf1  = arena(1024);
    float* biasf2  = arena(1024);
    float* watt1   = arena(8 * 512);
    float* watt2   = arena(8 * 512);
    float* Wc_rna  = arena((size_t)HIDd * RNAd);
    float* Wc_prot = arena((size_t)HIDd * PROTd);
    float* bc_rna  = arena(RNAd);
    float* bc_prot = arena(PROTd);

    // ---- side stream + events (created/destroyed every call; host objects) ----
    cudaStream_t sP;
    cudaStreamCreateWithFlags(&sP, cudaStreamNonBlocking);
    cudaEvent_t ev[8];
    for (int i = 0; i < 8; i++) cudaEventCreateWithFlags(&ev[i], cudaEventDisableTiming);

    // ======= FORK 1: prep + CSR on sP  ||  embed GEMMs on stream 0 =======
    cudaEventRecord(ev[0], 0);
    cudaStreamWaitEvent(sP, ev[0], 0);

    {   // side stream: all weight prep + CSR build
        Jobs jobs;
        int jc = 0;
        auto addj = [&](const float* s1, const float* s2, float* d, int n, int w1, int w2, int mode) {
            jobs.j[jc++] = Job{s1, s2, d, n, w1, w2, mode};
        };
        addj(g1_ws, l1_w, Bf1, 512 * 1024, 512, 512, 1);
        addj(g2_ws, l2_w, Bf2, 512 * 1024, 512, 512, 1);
        addj(g1_b,  l1_b, biasf1, 1024, 512, 0, 2);
        addj(g2_b,  l2_b, biasf2, 1024, 512, 0, 2);
        jobs.cnt = jc;
        prep_k<<<dim3(64, jc), 256, 0, sP>>>(jobs);

        wattn2_k<<<16, 128, 0, sP>>>(g1_ws, g1_wd, g1_as, g1_ad,
                                     g2_ws, g2_wd, g2_as, g2_ad, watt1, watt2);

        gemm(dr_w, EMBd, rr_w, RNAd,  Wc_rna,  RNAd,  nullptr, HIDd, RNAd,  EMBd, 0, nullptr, sP);
        gemm(dp_w, EMBd, rp_w, PROTd, Wc_prot, PROTd, nullptr, HIDd, PROTd, EMBd, 0, nullptr, sP);
        bcomb_k<<<(RNAd + 127) / 128, 128, 0, sP>>>(dr_b, rr_w, rr_b, bc_rna, RNAd, EMBd);
        bcomb_k<<<(PROTd + 127) / 128, 128, 0, sP>>>(dp_b, rp_w, rp_b, bc_prot, PROTd, EMBd);

        zero_deg_k<<<(Nn + 255) / 256, 256, 0, sP>>>(deg);
        hist_k<<<(Ee + 255) / 256, 256, 0, sP>>>(dst, deg);
        scan_k<<<1, SCAN_T, 0, sP>>>(deg, roff, cur);
        bucket_k<<<(Ee + 255) / 256, 256, 0, sP>>>(dst, cur, eord);
    }

    // main stream: input embeddings (depend only on x)
    gemm(x,        INWd, W_rna,  EMBd, h0,        HDd, b_rna,  Nn, EMBd, RNAd,  0);
    gemm(x + RNAd, INWd, W_prot, EMBd, h0 + EMBd, HDd, b_prot, Nn, EMBd, PROTd, 0);

    // join prep back to main
    cudaEventRecord(ev[1], sP);
    cudaStreamWaitEvent(0, ev[1], 0);

    // ======= GAT layer 1: attn8 on sP || fz GEMM on 0 =======
    cudaEventRecord(ev[2], 0);
    cudaStreamWaitEvent(sP, ev[2], 0);
    attn8_k<<<Nn, 256, 0, sP>>>(h0, watt1, asrc, adst);
    cudaEventRecord(ev[3], sP);

    gemm(h0, HDd, Bf1, 1024, fz, 1024, biasf1, Nn, 1024, HDd, 0, msg);

    cudaStreamWaitEvent(0, ev[3], 0);
    agg_fused_k<<<Nn, 128>>>(src, eord, roff, asrc, adst, msg, fz, buf);

    // ======= GAT layer 2 =======
    cudaEventRecord(ev[4], 0);
    cudaStreamWaitEvent(sP, ev[4], 0);
    attn8_k<<<Nn, 256, 0, sP>>>(buf, watt2, asrc, adst);
    cudaEventRecord(ev[5], sP);

    gemm(buf, HDd, Bf2, 1024, fz, 1024, biasf2, Nn, 1024, HDd, 0, msg);

    cudaStreamWaitEvent(0, ev[5], 0);
    agg_fused_k<<<Nn, 128>>>(src, eord, roff, asrc, adst, msg, fz, h0);

    // ======= embedding =======
    gemm(h0, HDd, agg_w, HIDd, out_emb, HIDd, agg_b, Nn, HIDd, HDd, 1);

    // ======= collapsed recon: out_prot on sP || out_rna on 0 =======
    cudaEventRecord(ev[6], 0);
    cudaStreamWaitEvent(sP, ev[6], 0);
    gemm(out_emb, HIDd, Wc_prot, PROTd, out_prot, PROTd, bc_prot, Nn, PROTd, HIDd, 0, nullptr, sP);
    cudaEventRecord(ev[7], sP);

    gemm(out_emb, HIDd, Wc_rna, RNAd, out_rna, RNAd, bc_rna, Nn, RNAd, HIDd, 0);

    cudaStreamWaitEvent(0, ev[7], 0);

    for (int i = 0; i < 8; i++) cudaEventDestroy(ev[i]);
    cudaStreamDestroy(sP);
}